// round 7
// baseline (speedup 1.0000x reference)
#include <cuda_runtime.h>
#include <cuda_fp16.h>
#include <math.h>
#include <stdint.h>

// ---------------------------------------------------------------------------
// Problem constants
// ---------------------------------------------------------------------------
#define NN        87381     // total nodes = (4^9-1)/3
#define NI        21845     // internal nodes
#define LEAF_N    65536
#define LEAF_S    21845

// ---------------------------------------------------------------------------
// Device scratch (static — no allocation allowed)
// ---------------------------------------------------------------------------
__device__ float  g_xiou[NI * 768];          // internal-node iou preactivations
__device__ float  g_xfq[NI * 512];           // cols 0-255: x_f, 256-511: q
__device__ __half g_hu[16384 * 1024];        // cols 0-767: h_iou, 768-1023: h_f
__device__ __half g_kkvv[65536 * 512];       // cols 0-255: k, 256-511: v
__device__ __half g_att[16384 * 256];
__device__ __half g_hatt[16384 * 256];
__device__ __half g_xh[NN * 256];            // x as fp16
__device__ __half g_hh[NN * 256];            // h as fp16

// weight rows (transposed, fp16 hi/lo). row index == bias index.
#define WT_IOU  0       // 768 rows
#define WT_FQ   768     // 512 rows (f, q)
#define WT_KV   1280    // 512 rows (k, v)
#define WT_L    1792    // 256 rows
#define WT_U    2048    // 1024 rows (uiou, uf)
__device__ __half g_wthi[3072 * 256];
__device__ __half g_wtlo[3072 * 256];
__device__ float  g_bias[3072];

// ---------------------------------------------------------------------------
// PTX helpers (sm_80+ — safe for plain sm_103 ptxas target)
// ---------------------------------------------------------------------------
__device__ __forceinline__ uint32_t s2u(const void* p) {
    uint32_t a;
    asm("{ .reg .u64 t; cvta.to.shared.u64 t, %1; cvt.u32.u64 %0, t; }"
        : "=r"(a) : "l"(p));
    return a;
}
__device__ __forceinline__ void cpa16(uint32_t dst, const void* src, int nbytes) {
    asm volatile("cp.async.cg.shared.global [%0], [%1], 16, %2;"
                 :: "r"(dst), "l"(src), "r"(nbytes) : "memory");
}
__device__ __forceinline__ void cpa_commit() {
    asm volatile("cp.async.commit_group;" ::: "memory");
}
__device__ __forceinline__ void ldm4(uint32_t* r, uint32_t addr) {
    asm volatile("ldmatrix.sync.aligned.m8n8.x4.shared.b16 {%0,%1,%2,%3}, [%4];"
                 : "=r"(r[0]), "=r"(r[1]), "=r"(r[2]), "=r"(r[3]) : "r"(addr));
}
__device__ __forceinline__ void mma16816(float* c, const uint32_t* a, const uint32_t* b) {
    asm volatile(
        "mma.sync.aligned.m16n8k16.row.col.f32.f16.f16.f32 "
        "{%0,%1,%2,%3}, {%4,%5,%6,%7}, {%8,%9}, {%0,%1,%2,%3};"
        : "+f"(c[0]), "+f"(c[1]), "+f"(c[2]), "+f"(c[3])
        : "r"(a[0]), "r"(a[1]), "r"(a[2]), "r"(a[3]), "r"(b[0]), "r"(b[1]));
}
__device__ __forceinline__ uint32_t swadr(uint32_t base, int row, int gran) {
    return base + row * 128 + ((gran ^ (row & 7)) << 4);
}
__device__ __forceinline__ uint32_t packh(__half a, __half b) {
    return ((uint32_t)__half_as_ushort(b) << 16) | __half_as_ushort(a);
}
__device__ __forceinline__ float sigm(float x) { return 1.f / (1.f + expf(-x)); }

// ---------------------------------------------------------------------------
// fp16 HMMA GEMM:  C[M, Ntot] = A[M,256] @ Wt^T + bias
//   CTA tile 128x128, 8 warps (2m x 4n), warp 64x32, k-chunk 64 x4, 3-stage
// ---------------------------------------------------------------------------
#define STG    49152
#define OA     0
#define OBH    16384
#define OBL    32768
#define GSMEM  (3 * STG)

__global__ void __launch_bounds__(256, 1)
gemm_f16(const __half* __restrict__ A,
         const __half* __restrict__ Bhi,
         const __half* __restrict__ Blo,
         const float* __restrict__ bias,
         float* __restrict__ C,
         __half* __restrict__ Ch,
         int M, int Ntot)
{
    extern __shared__ char smem[];
    const uint32_t sb = s2u(smem);
    const int tid  = threadIdx.x;
    const int lane = tid & 31;
    const int wid  = tid >> 5;
    const int wm   = wid & 1;
    const int wn   = wid >> 1;
    const int bm   = blockIdx.x * 128;
    const int n0   = blockIdx.y * 128;

    float acc[4][4][4];
    #pragma unroll
    for (int a = 0; a < 4; a++)
        #pragma unroll
        for (int b = 0; b < 4; b++)
            #pragma unroll
            for (int c = 0; c < 4; c++) acc[a][b][c] = 0.f;

    auto stage_chunk = [&](int kc) {
        uint32_t sa = sb + (kc % 3) * STG;
        #pragma unroll
        for (int t = 0; t < 4; t++) {
            int i = tid + t * 256;
            int row = i >> 3, g = i & 7;
            uint32_t d = row * 128 + ((g ^ (row & 7)) << 4);
            int  arow = bm + row;
            int  av   = arow < M ? 16 : 0;
            size_t as = (size_t)(arow < M ? arow : 0) * 256 + kc * 64 + g * 8;
            size_t bs = (size_t)(n0 + row) * 256 + kc * 64 + g * 8;
            cpa16(sa + OA  + d, A + as, av);
            cpa16(sa + OBH + d, Bhi + bs, 16);
            cpa16(sa + OBL + d, Blo + bs, 16);
        }
        cpa_commit();
    };

    stage_chunk(0);
    stage_chunk(1);

    for (int kc = 0; kc < 4; kc++) {
        if (kc < 3)
            asm volatile("cp.async.wait_group 1;" ::: "memory");
        else
            asm volatile("cp.async.wait_group 0;" ::: "memory");
        __syncthreads();
        if (kc + 2 < 4) stage_chunk(kc + 2);

        const uint32_t sa = sb + (kc % 3) * STG;
        #pragma unroll
        for (int ks = 0; ks < 4; ks++) {
            uint32_t af[4][4], bh[2][4], bl[2][4];
            #pragma unroll
            for (int mi = 0; mi < 4; mi++) {
                int rA = wm * 64 + mi * 16 + (lane & 15);
                int gA = 2 * ks + (lane >> 4);
                ldm4(af[mi], swadr(sa + OA, rA, gA));
            }
            #pragma unroll
            for (int bi = 0; bi < 2; bi++) {
                int rB = wn * 32 + bi * 16 + (lane & 7) + ((lane >> 4) << 3);
                int gB = 2 * ks + ((lane >> 3) & 1);
                ldm4(bh[bi], swadr(sa + OBH, rB, gB));
                ldm4(bl[bi], swadr(sa + OBL, rB, gB));
            }
            #pragma unroll
            for (int mi = 0; mi < 4; mi++)
                #pragma unroll
                for (int nf = 0; nf < 4; nf++)
                    mma16816(acc[mi][nf], af[mi], &bh[nf >> 1][(nf & 1) * 2]);
            #pragma unroll
            for (int mi = 0; mi < 4; mi++)
                #pragma unroll
                for (int nf = 0; nf < 4; nf++)
                    mma16816(acc[mi][nf], af[mi], &bl[nf >> 1][(nf & 1) * 2]);
        }
        __syncthreads();
    }

    #pragma unroll
    for (int mi = 0; mi < 4; mi++) {
        #pragma unroll
        for (int nf = 0; nf < 4; nf++) {
            int r0  = bm + wm * 64 + mi * 16 + (lane >> 2);
            int col = n0 + wn * 32 + nf * 8 + ((lane & 3) << 1);
            float2 b2 = *(const float2*)&bias[col];
            float v0 = acc[mi][nf][0] + b2.x;
            float v1 = acc[mi][nf][1] + b2.y;
            float v2 = acc[mi][nf][2] + b2.x;
            float v3 = acc[mi][nf][3] + b2.y;
            if (r0 < M) {
                size_t o = (size_t)r0 * Ntot + col;
                if (C)  *(float2*)&C[o] = make_float2(v0, v1);
                if (Ch) *(uint32_t*)&Ch[o] =
                    packh(__float2half_rn(v0), __float2half_rn(v1));
            }
            if (r0 + 8 < M) {
                size_t o = (size_t)(r0 + 8) * Ntot + col;
                if (C)  *(float2*)&C[o] = make_float2(v2, v3);
                if (Ch) *(uint32_t*)&Ch[o] =
                    packh(__float2half_rn(v2), __float2half_rn(v3));
            }
        }
    }
}

// ---------------------------------------------------------------------------
// Leaf-fused GEMM: computes xiou for 64 leaves x 64 channels (192 cols,
// gate-interleaved octets [i|o|u] x 8ch) and applies the LSTM leaf activation
// in the epilogue. Writes h_out/c_out/hh directly — xiou never hits DRAM.
// 8 warps (2m x 4n), warp tile 32x48. 2-stage cp.async.
// ---------------------------------------------------------------------------
#define STG2   57344
#define OA2    0
#define OBH2   8192
#define OBL2   32768
#define GSMEM2 (2 * STG2)

__global__ void __launch_bounds__(256, 1)
gemm_leaf(const __half* __restrict__ A,        // xh (full node table)
          const __half* __restrict__ Whi,      // WT_IOU rows of g_wthi
          const __half* __restrict__ Wlo,
          const float* __restrict__ b_iou,
          float* __restrict__ h_out,
          float* __restrict__ c_out,
          __half* __restrict__ hh)
{
    extern __shared__ char smem[];
    const uint32_t sb = s2u(smem);
    const int tid  = threadIdx.x;
    const int lane = tid & 31;
    const int wid  = tid >> 5;
    const int wm   = wid & 1;
    const int wn   = wid >> 1;
    const int bm   = blockIdx.x * 64;       // leaf-local row base
    const int j0   = blockIdx.y * 64;       // channel base

    float acc[2][6][4];
    #pragma unroll
    for (int a = 0; a < 2; a++)
        #pragma unroll
        for (int b = 0; b < 6; b++)
            #pragma unroll
            for (int c = 0; c < 4; c++) acc[a][b][c] = 0.f;

    auto stage_chunk = [&](int kc) {
        uint32_t sa = sb + (kc & 1) * STG2;
        // A: 64 rows x 64 k
        #pragma unroll
        for (int t = 0; t < 2; t++) {
            int i = tid + t * 256;
            int row = i >> 3, g = i & 7;
            uint32_t d = row * 128 + ((g ^ (row & 7)) << 4);
            size_t as = (size_t)(LEAF_S + bm + row) * 256 + kc * 64 + g * 8;
            cpa16(sa + OA2 + d, A + as, 16);
        }
        // B: 192 rows (gate-interleaved) x 64 k, hi + lo
        #pragma unroll
        for (int t = 0; t < 6; t++) {
            int i = tid + t * 256;           // 0..1535
            int rr = i >> 3, g = i & 7;
            int oct = rr / 24, rem = rr % 24;
            int gate = rem >> 3, cpos = rem & 7;
            int wtrow = gate * 256 + j0 + oct * 8 + cpos;
            uint32_t d = rr * 128 + ((g ^ (rr & 7)) << 4);
            size_t bs = (size_t)wtrow * 256 + kc * 64 + g * 8;
            cpa16(sa + OBH2 + d, Whi + bs, 16);
            cpa16(sa + OBL2 + d, Wlo + bs, 16);
        }
        cpa_commit();
    };

    stage_chunk(0);
    for (int kc = 0; kc < 4; kc++) {
        if (kc < 3) {
            stage_chunk(kc + 1);
            asm volatile("cp.async.wait_group 1;" ::: "memory");
        } else {
            asm volatile("cp.async.wait_group 0;" ::: "memory");
        }
        __syncthreads();

        const uint32_t sa = sb + (kc & 1) * STG2;
        #pragma unroll
        for (int ks = 0; ks < 4; ks++) {
            uint32_t af[2][4], bh[3][4], bl[3][4];
            #pragma unroll
            for (int mi = 0; mi < 2; mi++) {
                int rA = wm * 32 + mi * 16 + (lane & 15);
                int gA = 2 * ks + (lane >> 4);
                ldm4(af[mi], swadr(sa + OA2, rA, gA));
            }
            #pragma unroll
            for (int bi = 0; bi < 3; bi++) {
                int rB = wn * 48 + bi * 16 + (lane & 7) + ((lane >> 4) << 3);
                int gB = 2 * ks + ((lane >> 3) & 1);
                ldm4(bh[bi], swadr(sa + OBH2, rB, gB));
                ldm4(bl[bi], swadr(sa + OBL2, rB, gB));
            }
            #pragma unroll
            for (int mi = 0; mi < 2; mi++)
                #pragma unroll
                for (int nf = 0; nf < 6; nf++)
                    mma16816(acc[mi][nf], af[mi], &bh[nf >> 1][(nf & 1) * 2]);
            #pragma unroll
            for (int mi = 0; mi < 2; mi++)
                #pragma unroll
                for (int nf = 0; nf < 6; nf++)
                    mma16816(acc[mi][nf], af[mi], &bl[nf >> 1][(nf & 1) * 2]);
        }
        __syncthreads();
    }

    // ---- fused leaf activation epilogue
    #pragma unroll
    for (int mi = 0; mi < 2; mi++) {
        #pragma unroll
        for (int ol = 0; ol < 2; ol++) {
            const float* ai = acc[mi][ol * 3 + 0];
            const float* ao = acc[mi][ol * 3 + 1];
            const float* au = acc[mi][ol * 3 + 2];
            int oct = wn * 2 + ol;
            int ch  = j0 + oct * 8 + ((lane & 3) << 1);
            float2 bi2 = *(const float2*)&b_iou[ch];
            float2 bo2 = *(const float2*)&b_iou[256 + ch];
            float2 bu2 = *(const float2*)&b_iou[512 + ch];
            int m = wm * 32 + mi * 16 + (lane >> 2);
            #pragma unroll
            for (int half = 0; half < 2; half++) {
                size_t node = (size_t)(LEAF_S + bm + m + half * 8);
                float i0 = ai[half * 2 + 0] + bi2.x, i1 = ai[half * 2 + 1] + bi2.y;
                float o0 = ao[half * 2 + 0] + bo2.x, o1 = ao[half * 2 + 1] + bo2.y;
                float u0 = au[half * 2 + 0] + bu2.x, u1 = au[half * 2 + 1] + bu2.y;
                float c0 = sigm(i0) * tanhf(u0);
                float c1 = sigm(i1) * tanhf(u1);
                float h0 = sigm(o0) * tanhf(c0);
                float h1 = sigm(o1) * tanhf(c1);
                size_t off = node * 256 + ch;
                *(float2*)&h_out[off] = make_float2(h0, h1);
                *(float2*)&c_out[off] = make_float2(c0, c1);
                *(uint32_t*)&hh[off] = packh(__float2half_rn(h0), __float2half_rn(h1));
            }
        }
    }
}

// ---------------------------------------------------------------------------
// Fused small-level kernel (levels with n <= 64): one CTA = 2 nodes, all
// phases (KV GEMM, attention, Wl, U, combine) done SIMT fp32 with smem.
// ---------------------------------------------------------------------------
__global__ void __launch_bounds__(512, 1)
fused_level(const float* __restrict__ xiou,
            const float* __restrict__ xfq,
            const float* __restrict__ Wk,  const float* __restrict__ bk_,
            const float* __restrict__ Wv,  const float* __restrict__ bv_,
            const float* __restrict__ Wl,  const float* __restrict__ bl_,
            const float* __restrict__ Uiou_w, const float* __restrict__ Uiou_b,
            const float* __restrict__ Uf_w,   const float* __restrict__ Uf_b,
            float* __restrict__ h_out, float* __restrict__ c_out,
            int s0, int cs, int n)
{
    __shared__ float chs[8][256];
    __shared__ float kvs[8][512];
    __shared__ float atts[2][256];
    __shared__ float hatts[2][256];
    __shared__ float hus[2][1024];

    const int tid = threadIdx.x;
    const int node0 = blockIdx.x * 2;
    const int nn = (n - node0) < 2 ? (n - node0) : 2;

    // phase A: load children h
    for (int idx = tid; idx < 4 * nn * 256; idx += 512) {
        int r = idx >> 8, k = idx & 255;
        chs[r][k] = h_out[(size_t)(cs + node0 * 4 + r) * 256 + k];
    }
    __syncthreads();

    // phase B: kv = ch_h @ [Wk|Wv] + bias
    {
        int c = tid;
        const float* W = (c < 256) ? (Wk + c) : (Wv + (c - 256));
        float acc[8] = {0, 0, 0, 0, 0, 0, 0, 0};
        int rmax = 4 * nn;
        #pragma unroll 4
        for (int k = 0; k < 256; k++) {
            float w = W[(size_t)k * 256];
            #pragma unroll
            for (int r = 0; r < 8; r++)
                acc[r] += chs[r][k] * w;
        }
        float b = (c < 256) ? bk_[c] : bv_[c - 256];
        for (int r = 0; r < rmax; r++) kvs[r][c] = acc[r] + b;
    }
    __syncthreads();

    // phase C: attention (i = node, d = dim; head = d>>5)
    {
        int i = tid >> 8, d = tid & 255;
        if (i < nn) {
            float qv = xfq[(size_t)(s0 + node0 + i) * 512 + 256 + d];
            float logit[4];
            #pragma unroll
            for (int k = 0; k < 4; k++) {
                float p = qv * kvs[i * 4 + k][d];
                #pragma unroll
                for (int off = 16; off > 0; off >>= 1)
                    p += __shfl_xor_sync(0xffffffffu, p, off);
                logit[k] = p * 0.1767766952966369f;
            }
            float mx = fmaxf(fmaxf(logit[0], logit[1]), fmaxf(logit[2], logit[3]));
            float e[4], s = 0.f;
            #pragma unroll
            for (int k = 0; k < 4; k++) { e[k] = expf(logit[k] - mx); s += e[k]; }
            float inv = 1.f / s;
            float o = 0.f;
            #pragma unroll
            for (int k = 0; k < 4; k++)
                o += (e[k] * inv) * kvs[i * 4 + k][256 + d];
            atts[i][d] = o;
        }
    }
    __syncthreads();

    // phase D: hatt = att @ Wl + bl (256 threads)
    if (tid < 256) {
        int c = tid;
        float a0 = 0.f, a1 = 0.f;
        #pragma unroll 4
        for (int k = 0; k < 256; k++) {
            float w = Wl[(size_t)k * 256 + c];
            a0 += atts[0][k] * w;
            a1 += atts[1][k] * w;
        }
        hatts[0][c] = a0 + bl_[c];
        hatts[1][c] = a1 + bl_[c];
    }
    __syncthreads();

    // phase E: hu = hatt @ [Uiou|Uf] + bias (1024 cols, 2 passes)
    #pragma unroll
    for (int pass = 0; pass < 2; pass++) {
        int cc = tid + pass * 512;
        float a0 = 0.f, a1 = 0.f, b;
        if (cc < 768) {
            #pragma unroll 4
            for (int k = 0; k < 256; k++) {
                float w = Uiou_w[(size_t)k * 768 + cc];
                a0 += hatts[0][k] * w;
                a1 += hatts[1][k] * w;
            }
            b = Uiou_b[cc];
        } else {
            int c2 = cc - 768;
            #pragma unroll 4
            for (int k = 0; k < 256; k++) {
                float w = Uf_w[(size_t)k * 256 + c2];
                a0 += hatts[0][k] * w;
                a1 += hatts[1][k] * w;
            }
            b = Uf_b[c2];
        }
        hus[0][cc] = a0 + b;
        hus[1][cc] = a1 + b;
    }
    __syncthreads();

    // phase F: combine
    {
        int i = tid >> 8, j = tid & 255;
        if (i < nn) {
            size_t g = (size_t)(s0 + node0 + i);
            float ig = xiou[g * 768 + j]       + hus[i][j];
            float og = xiou[g * 768 + 256 + j] + hus[i][256 + j];
            float ug = xiou[g * 768 + 512 + j] + hus[i][512 + j];
            float f  = sigm(xfq[g * 512 + j]   + hus[i][768 + j]);
            size_t cb = (size_t)(cs + (node0 + i) * 4) * 256 + j;
            float csum = c_out[cb] + c_out[cb + 256] + c_out[cb + 512] + c_out[cb + 768];
            float cv = sigm(ig) * tanhf(ug) + f * csum;
            float hv = sigm(og) * tanhf(cv);
            h_out[g * 256 + j] = hv;
            c_out[g * 256 + j] = cv;
        }
    }
}

// ---------------------------------------------------------------------------
// Weight prep: coalesced transpose W[256, N] -> rows [N,256], fp16 hi/lo
// ---------------------------------------------------------------------------
__global__ void prep_w(const float* __restrict__ W,
                       __half* __restrict__ hi,
                       __half* __restrict__ lo, int N)
{
    __shared__ float tile[256][33];
    const int n0 = blockIdx.x * 32;
    const int tx = threadIdx.x & 31;
    const int ty = threadIdx.x >> 5;
    for (int k = ty; k < 256; k += 8)
        tile[k][tx] = W[(size_t)k * N + n0 + tx];
    __syncthreads();
    for (int nr = ty * 4; nr < ty * 4 + 4; nr++) {
        for (int k = tx; k < 256; k += 32) {
            float v = tile[k][nr];
            __half h = __float2half_rn(v);
            hi[(size_t)(n0 + nr) * 256 + k] = h;
            lo[(size_t)(n0 + nr) * 256 + k] = __float2half_rn(v - __half2float(h));
        }
    }
}

__global__ void split_x(const float* __restrict__ x,
                        __half* __restrict__ xh, int total4)
{
    int i = blockIdx.x * blockDim.x + threadIdx.x;
    if (i >= total4) return;
    float4 v = *(const float4*)&x[i * 4];
    uint2 p;
    p.x = packh(__float2half_rn(v.x), __float2half_rn(v.y));
    p.y = packh(__float2half_rn(v.z), __float2half_rn(v.w));
    *(uint2*)&xh[i * 4] = p;
}

// ---------------------------------------------------------------------------
// Attention (HMMA levels): one block per node, warp per head
// ---------------------------------------------------------------------------
__global__ void attn_kernel(const float* __restrict__ xfq,
                            const __half* __restrict__ kkvv,
                            __half* __restrict__ out,
                            int s0)
{
    const int node = blockIdx.x;
    const int d = threadIdx.x;
    const float qv = xfq[(size_t)(s0 + node) * 512 + 256 + d];

    float logit[4];
    #pragma unroll
    for (int k = 0; k < 4; k++) {
        float p = qv * __half2float(kkvv[((size_t)(node * 4 + k)) * 512 + d]);
        #pragma unroll
        for (int off = 16; off > 0; off >>= 1)
            p += __shfl_xor_sync(0xffffffffu, p, off);
        logit[k] = p * 0.1767766952966369f;
    }
    float mx = fmaxf(fmaxf(logit[0], logit[1]), fmaxf(logit[2], logit[3]));
    float e[4], s = 0.f;
    #pragma unroll
    for (int k = 0; k < 4; k++) { e[k] = expf(logit[k] - mx); s += e[k]; }
    const float inv = 1.f / s;

    float o = 0.f;
    #pragma unroll
    for (int k = 0; k < 4; k++)
        o += (e[k] * inv) * __half2float(kkvv[((size_t)(node * 4 + k)) * 512 + 256 + d]);
    out[(size_t)node * 256 + d] = __float2half_rn(o);
}

// ---------------------------------------------------------------------------
// Combine (HMMA levels)
// ---------------------------------------------------------------------------
__global__ void combine_kernel(const float* __restrict__ xiou,
                               const float* __restrict__ xfq,
                               const __half* __restrict__ hu,
                               float* __restrict__ h_out,
                               float* __restrict__ c_out,
                               __half* __restrict__ hh,
                               int s0, int child_start)
{
    const int i = blockIdx.x;
    const int j = threadIdx.x;
    const size_t gr = (size_t)(s0 + i);

    const float ig = xiou[gr * 768 + j]       + __half2float(hu[(size_t)i * 1024 + j]);
    const float og = xiou[gr * 768 + 256 + j] + __half2float(hu[(size_t)i * 1024 + 256 + j]);
    const float ug = xiou[gr * 768 + 512 + j] + __half2float(hu[(size_t)i * 1024 + 512 + j]);
    const float f  = sigm(xfq[gr * 512 + j]   + __half2float(hu[(size_t)i * 1024 + 768 + j]));

    const size_t cb = (size_t)(child_start + i * 4) * 256 + j;
    const float csum = c_out[cb] + c_out[cb + 256] + c_out[cb + 512] + c_out[cb + 768];

    const float c = sigm(ig) * tanhf(ug) + f * csum;
    const float h = sigm(og) * tanhf(c);
    h_out[gr * 256 + j] = h;
    c_out[gr * 256 + j] = c;
    hh[gr * 256 + j] = __float2half_rn(h);
}

// ---------------------------------------------------------------------------
// Launch
// ---------------------------------------------------------------------------
extern "C" void kernel_launch(void* const* d_in, const int* in_sizes, int n_in,
                              void* d_out, int out_size)
{
    const float* x      = (const float*)d_in[0];
    const float* W_iou  = (const float*)d_in[1];
    const float* b_iou  = (const float*)d_in[2];
    const float* W_f    = (const float*)d_in[3];
    const float* b_f    = (const float*)d_in[4];
    const float* Wq     = (const float*)d_in[5];
    const float* bq     = (const float*)d_in[6];
    const float* Wk     = (const float*)d_in[7];
    const float* bk     = (const float*)d_in[8];
    const float* Wv     = (const float*)d_in[9];
    const float* bv     = (const float*)d_in[10];
    const float* Wl     = (const float*)d_in[11];
    const float* bl     = (const float*)d_in[12];
    const float* Uiou_w = (const float*)d_in[13];
    const float* Uiou_b = (const float*)d_in[14];
    const float* Uf_w   = (const float*)d_in[15];
    const float* Uf_b   = (const float*)d_in[16];

    float* h_out = (float*)d_out;
    float* c_out = h_out + (size_t)NN * 256;

    float *xiou, *xfq, *bias;
    __half *hu, *kkvv, *att, *hatt, *xh, *hh, *wthi, *wtlo;
    cudaGetSymbolAddress((void**)&xiou, g_xiou);
    cudaGetSymbolAddress((void**)&xfq,  g_xfq);
    cudaGetSymbolAddress((void**)&hu,   g_hu);
    cudaGetSymbolAddress((void**)&bias, g_bias);
    cudaGetSymbolAddress((void**)&kkvv, g_kkvv);
    cudaGetSymbolAddress((void**)&att,  g_att);
    cudaGetSymbolAddress((void**)&hatt, g_hatt);
    cudaGetSymbolAddress((void**)&xh,   g_xh);
    cudaGetSymbolAddress((void**)&hh,   g_hh);
    cudaGetSymbolAddress((void**)&wthi, g_wthi);
    cudaGetSymbolAddress((void**)&wtlo, g_wtlo);

    cudaFuncSetAttribute(gemm_f16, cudaFuncAttributeMaxDynamicSharedMemorySize, GSMEM);
    cudaFuncSetAttribute(gemm_leaf, cudaFuncAttributeMaxDynamicSharedMemorySize, GSMEM2);

    auto GEMM = [&](const __half* A, int wt, float* C, __half* Ch, int M, int Ntot) {
        dim3 grid((M + 127) / 128, Ntot / 128);
        gemm_f16<<<grid, 256, GSMEM>>>(A, wthi + (size_t)wt * 256,
                                       wtlo + (size_t)wt * 256,
                                       bias + wt, C, Ch, M, Ntot);
    };

    // ---- weight prep ----
    prep_w<<<24, 256>>>(W_iou,  wthi + (size_t)WT_IOU * 256,        wtlo + (size_t)WT_IOU * 256,        768);
    prep_w<<< 8, 256>>>(W_f,    wthi + (size_t)WT_FQ * 256,         wtlo + (size_t)WT_FQ * 256,         256);
    prep_w<<< 8, 256>>>(Wq,     wthi + (size_t)(WT_FQ + 256) * 256, wtlo + (size_t)(WT_FQ + 256) * 256, 256);
    prep_w<<< 8, 256>>>(Wk,     wthi + (size_t)WT_KV * 256,         wtlo + (size_t)WT_KV * 256,         256);
    prep_w<<< 8, 256>>>(Wv,     wthi + (size_t)(WT_KV + 256) * 256, wtlo + (size_t)(WT_KV + 256) * 256, 256);
    prep_w<<< 8, 256>>>(Wl,     wthi + (size_t)WT_L * 256,          wtlo + (size_t)WT_L * 256,          256);
    prep_w<<<24, 256>>>(Uiou_w, wthi + (size_t)WT_U * 256,          wtlo + (size_t)WT_U * 256,          768);
    prep_w<<< 8, 256>>>(Uf_w,   wthi + (size_t)(WT_U + 768) * 256,  wtlo + (size_t)(WT_U + 768) * 256,  256);

    // ---- bias concat ----
    cudaMemcpyAsync(bias + WT_IOU,      b_iou,  768 * 4, cudaMemcpyDeviceToDevice, 0);
    cudaMemcpyAsync(bias + WT_FQ,       b_f,    256 * 4, cudaMemcpyDeviceToDevice, 0);
    cudaMemcpyAsync(bias + WT_FQ + 256, bq,     256 * 4, cudaMemcpyDeviceToDevice, 0);
    cudaMemcpyAsync(bias + WT_KV,       bk,     256 * 4, cudaMemcpyDeviceToDevice, 0);
    cudaMemcpyAsync(bias + WT_KV + 256, bv,     256 * 4, cudaMemcpyDeviceToDevice, 0);
    cudaMemcpyAsync(bias + WT_L,        bl,     256 * 4, cudaMemcpyDeviceToDevice, 0);
    cudaMemcpyAsync(bias + WT_U,        Uiou_b, 768 * 4, cudaMemcpyDeviceToDevice, 0);
    cudaMemcpyAsync(bias + WT_U + 768,  Uf_b,   256 * 4, cudaMemcpyDeviceToDevice, 0);

    // ---- split x, precompute GEMMs (internal nodes only for xiou/xfq) ----
    const int tot4 = NN * 256 / 4;
    split_x<<<(tot4 + 255) / 256, 256>>>(x, xh, tot4);
    GEMM(xh, WT_IOU, xiou, nullptr, NI, 768);
    GEMM(xh, WT_FQ,  xfq,  nullptr, NI, 512);

    // ---- leaf level: fused GEMM + activation ----
    gemm_leaf<<<dim3(LEAF_N / 64, 4), 256, GSMEM2>>>(xh, wthi, wtlo, b_iou,
                                                     h_out, c_out, hh);

    // ---- internal levels, bottom-up ----
    const int starts[9] = {0, 1, 5, 21, 85, 341, 1365, 5461, 21845};
    for (int l = 7; l >= 4; l--) {
        const int n  = 1 << (2 * l);
        const int s0 = starts[l];
        const int cs = starts[l + 1];
        const int nK = n * 4;
        const __half* chh = hh + (size_t)cs * 256;

        GEMM(chh, WT_KV, nullptr, kkvv, nK, 512);
        attn_kernel<<<n, 256>>>(xfq, kkvv, att, s0);
        GEMM(att, WT_L, nullptr, hatt, n, 256);
        GEMM(hatt, WT_U, nullptr, hu, n, 1024);
        combine_kernel<<<n, 256>>>(xiou, xfq, hu, h_out, c_out, hh, s0, cs);
    }
    for (int l = 3; l >= 0; l--) {
        const int n  = 1 << (2 * l);
        fused_level<<<(n + 1) / 2, 512>>>(xiou, xfq,
                                          Wk, bk, Wv, bv, Wl, bl,
                                          Uiou_w, Uiou_b, Uf_w, Uf_b,
                                          h_out, c_out,
                                          starts[l], starts[l + 1], n);
    }
}

// round 8
// speedup vs baseline: 1.2768x; 1.2768x over previous
#include <cuda_runtime.h>
#include <cuda_fp16.h>
#include <math.h>
#include <stdint.h>

// ---------------------------------------------------------------------------
// Problem constants
// ---------------------------------------------------------------------------
#define NN        87381     // total nodes = (4^9-1)/3
#define NI        21845     // internal nodes
#define LEAF_N    65536
#define LEAF_S    21845

// ---------------------------------------------------------------------------
// Device scratch (static — no allocation allowed)
// ---------------------------------------------------------------------------
__device__ float  g_xiou[NN * 768];          // iou preactivations (all nodes)
__device__ float  g_xfq[NI * 512];           // cols 0-255: x_f, 256-511: q
__device__ __half g_hu[16384 * 1024];        // cols 0-767: h_iou, 768-1023: h_f
__device__ __half g_kkvv[65536 * 512];       // cols 0-255: k, 256-511: v
__device__ __half g_att[16384 * 256];
__device__ __half g_hatt[16384 * 256];
__device__ __half g_xh[NN * 256];            // x as fp16
__device__ __half g_hh[NN * 256];            // h as fp16

// weight rows (transposed fp16). row index == bias index.
#define WT_IOU  0       // 768 rows
#define WT_FQ   768     // 512 rows (f, q)
#define WT_KV   1280    // 512 rows (k, v)
#define WT_L    1792    // 256 rows
#define WT_U    2048    // 1024 rows (uiou, uf)
__device__ __half g_wthi[3072 * 256];
__device__ float  g_bias[3072];

// ---------------------------------------------------------------------------
// PTX helpers (sm_80+ — safe for plain sm_103 ptxas target)
// ---------------------------------------------------------------------------
__device__ __forceinline__ uint32_t s2u(const void* p) {
    uint32_t a;
    asm("{ .reg .u64 t; cvta.to.shared.u64 t, %1; cvt.u32.u64 %0, t; }"
        : "=r"(a) : "l"(p));
    return a;
}
__device__ __forceinline__ void cpa16(uint32_t dst, const void* src, int nbytes) {
    asm volatile("cp.async.cg.shared.global [%0], [%1], 16, %2;"
                 :: "r"(dst), "l"(src), "r"(nbytes) : "memory");
}
__device__ __forceinline__ void cpa_commit() {
    asm volatile("cp.async.commit_group;" ::: "memory");
}
__device__ __forceinline__ void ldm4(uint32_t* r, uint32_t addr) {
    asm volatile("ldmatrix.sync.aligned.m8n8.x4.shared.b16 {%0,%1,%2,%3}, [%4];"
                 : "=r"(r[0]), "=r"(r[1]), "=r"(r[2]), "=r"(r[3]) : "r"(addr));
}
__device__ __forceinline__ void mma16816(float* c, const uint32_t* a, const uint32_t* b) {
    asm volatile(
        "mma.sync.aligned.m16n8k16.row.col.f32.f16.f16.f32 "
        "{%0,%1,%2,%3}, {%4,%5,%6,%7}, {%8,%9}, {%0,%1,%2,%3};"
        : "+f"(c[0]), "+f"(c[1]), "+f"(c[2]), "+f"(c[3])
        : "r"(a[0]), "r"(a[1]), "r"(a[2]), "r"(a[3]), "r"(b[0]), "r"(b[1]));
}
__device__ __forceinline__ uint32_t swadr(uint32_t base, int row, int gran) {
    return base + row * 128 + ((gran ^ (row & 7)) << 4);
}
__device__ __forceinline__ uint32_t packh(__half a, __half b) {
    return ((uint32_t)__half_as_ushort(b) << 16) | __half_as_ushort(a);
}
__device__ __forceinline__ float sigm(float x) { return 1.f / (1.f + expf(-x)); }

// ---------------------------------------------------------------------------
// fp16 HMMA GEMM:  C[M, Ntot] = A[M,256] @ Wt^T + bias   (single product)
//   CTA tile 128x128, 8 warps (2m x 4n), warp 64x32, k-chunk 64 x4, 3-stage
// ---------------------------------------------------------------------------
#define STG    32768
#define OA     0
#define OBH    16384
#define GSMEM  (3 * STG)   // 98304 bytes

__global__ void __launch_bounds__(256, 1)
gemm_f16(const __half* __restrict__ A,
         const __half* __restrict__ Bhi,
         const float* __restrict__ bias,
         float* __restrict__ C,
         __half* __restrict__ Ch,
         int M, int Ntot)
{
    extern __shared__ char smem[];
    const uint32_t sb = s2u(smem);
    const int tid  = threadIdx.x;
    const int lane = tid & 31;
    const int wid  = tid >> 5;
    const int wm   = wid & 1;
    const int wn   = wid >> 1;
    const int bm   = blockIdx.x * 128;
    const int n0   = blockIdx.y * 128;

    float acc[4][4][4];
    #pragma unroll
    for (int a = 0; a < 4; a++)
        #pragma unroll
        for (int b = 0; b < 4; b++)
            #pragma unroll
            for (int c = 0; c < 4; c++) acc[a][b][c] = 0.f;

    auto stage_chunk = [&](int kc) {
        uint32_t sa = sb + (kc % 3) * STG;
        #pragma unroll
        for (int t = 0; t < 4; t++) {
            int i = tid + t * 256;
            int row = i >> 3, g = i & 7;
            uint32_t d = row * 128 + ((g ^ (row & 7)) << 4);
            int  arow = bm + row;
            int  av   = arow < M ? 16 : 0;
            size_t as = (size_t)(arow < M ? arow : 0) * 256 + kc * 64 + g * 8;
            size_t bs = (size_t)(n0 + row) * 256 + kc * 64 + g * 8;
            cpa16(sa + OA  + d, A + as, av);
            cpa16(sa + OBH + d, Bhi + bs, 16);
        }
        cpa_commit();
    };

    stage_chunk(0);
    stage_chunk(1);

    for (int kc = 0; kc < 4; kc++) {
        if (kc < 3)
            asm volatile("cp.async.wait_group 1;" ::: "memory");
        else
            asm volatile("cp.async.wait_group 0;" ::: "memory");
        __syncthreads();
        if (kc + 2 < 4) stage_chunk(kc + 2);

        const uint32_t sa = sb + (kc % 3) * STG;
        #pragma unroll
        for (int ks = 0; ks < 4; ks++) {
            uint32_t af[4][4], bh[2][4];
            #pragma unroll
            for (int mi = 0; mi < 4; mi++) {
                int rA = wm * 64 + mi * 16 + (lane & 15);
                int gA = 2 * ks + (lane >> 4);
                ldm4(af[mi], swadr(sa + OA, rA, gA));
            }
            #pragma unroll
            for (int bi = 0; bi < 2; bi++) {
                int rB = wn * 32 + bi * 16 + (lane & 7) + ((lane >> 4) << 3);
                int gB = 2 * ks + ((lane >> 3) & 1);
                ldm4(bh[bi], swadr(sa + OBH, rB, gB));
            }
            #pragma unroll
            for (int mi = 0; mi < 4; mi++)
                #pragma unroll
                for (int nf = 0; nf < 4; nf++)
                    mma16816(acc[mi][nf], af[mi], &bh[nf >> 1][(nf & 1) * 2]);
        }
        __syncthreads();
    }

    #pragma unroll
    for (int mi = 0; mi < 4; mi++) {
        #pragma unroll
        for (int nf = 0; nf < 4; nf++) {
            int r0  = bm + wm * 64 + mi * 16 + (lane >> 2);
            int col = n0 + wn * 32 + nf * 8 + ((lane & 3) << 1);
            float2 b2 = *(const float2*)&bias[col];
            float v0 = acc[mi][nf][0] + b2.x;
            float v1 = acc[mi][nf][1] + b2.y;
            float v2 = acc[mi][nf][2] + b2.x;
            float v3 = acc[mi][nf][3] + b2.y;
            if (r0 < M) {
                size_t o = (size_t)r0 * Ntot + col;
                if (C)  *(float2*)&C[o] = make_float2(v0, v1);
                if (Ch) *(uint32_t*)&Ch[o] =
                    packh(__float2half_rn(v0), __float2half_rn(v1));
            }
            if (r0 + 8 < M) {
                size_t o = (size_t)(r0 + 8) * Ntot + col;
                if (C)  *(float2*)&C[o] = make_float2(v2, v3);
                if (Ch) *(uint32_t*)&Ch[o] =
                    packh(__float2half_rn(v2), __float2half_rn(v3));
            }
        }
    }
}

// ---------------------------------------------------------------------------
// Combined weight prep: one launch transposes all 8 matrices -> fp16 rows.
// 96 blocks total; block-to-matrix mapping via cumulative table.
// ---------------------------------------------------------------------------
struct PrepArgs {
    const float* W[8];
    int N[8];          // source column count
    int row_off[8];    // destination row offset in g_wthi
    int blk_cum[9];    // cumulative 32-col block counts
};

__global__ void prep_all(PrepArgs pa, __half* __restrict__ wthi)
{
    __shared__ float tile[256][33];
    int b = blockIdx.x;
    int m = 0;
    while (b >= pa.blk_cum[m + 1]) m++;
    const int n0 = (b - pa.blk_cum[m]) * 32;
    const float* W = pa.W[m];
    const int N = pa.N[m];
    __half* out = wthi + (size_t)pa.row_off[m] * 256;

    const int tx = threadIdx.x & 31;
    const int ty = threadIdx.x >> 5;
    for (int k = ty; k < 256; k += 8)
        tile[k][tx] = W[(size_t)k * N + n0 + tx];
    __syncthreads();
    for (int nr = ty * 4; nr < ty * 4 + 4; nr++)
        for (int k = tx; k < 256; k += 32)
            out[(size_t)(n0 + nr) * 256 + k] = __float2half_rn(tile[k][nr]);
}

__global__ void split_x(const float* __restrict__ x,
                        __half* __restrict__ xh, int total4)
{
    int i = blockIdx.x * blockDim.x + threadIdx.x;
    if (i >= total4) return;
    float4 v = *(const float4*)&x[i * 4];
    uint2 p;
    p.x = packh(__float2half_rn(v.x), __float2half_rn(v.y));
    p.y = packh(__float2half_rn(v.z), __float2half_rn(v.w));
    *(uint2*)&xh[i * 4] = p;
}

// ---------------------------------------------------------------------------
// Attention (HMMA levels): one block per node, warp per head
// ---------------------------------------------------------------------------
__global__ void attn_kernel(const float* __restrict__ xfq,
                            const __half* __restrict__ kkvv,
                            __half* __restrict__ out,
                            int s0)
{
    const int node = blockIdx.x;
    const int d = threadIdx.x;
    const float qv = xfq[(size_t)(s0 + node) * 512 + 256 + d];

    float logit[4];
    #pragma unroll
    for (int k = 0; k < 4; k++) {
        float p = qv * __half2float(kkvv[((size_t)(node * 4 + k)) * 512 + d]);
        #pragma unroll
        for (int off = 16; off > 0; off >>= 1)
            p += __shfl_xor_sync(0xffffffffu, p, off);
        logit[k] = p * 0.1767766952966369f;
    }
    float mx = fmaxf(fmaxf(logit[0], logit[1]), fmaxf(logit[2], logit[3]));
    float e[4], s = 0.f;
    #pragma unroll
    for (int k = 0; k < 4; k++) { e[k] = expf(logit[k] - mx); s += e[k]; }
    const float inv = 1.f / s;

    float o = 0.f;
    #pragma unroll
    for (int k = 0; k < 4; k++)
        o += (e[k] * inv) * __half2float(kkvv[((size_t)(node * 4 + k)) * 512 + 256 + d]);
    out[(size_t)node * 256 + d] = __float2half_rn(o);
}

// ---------------------------------------------------------------------------
// Elementwise
// ---------------------------------------------------------------------------
__global__ void leaf_kernel(const float* __restrict__ xiou,
                            float* __restrict__ h_out,
                            float* __restrict__ c_out,
                            __half* __restrict__ hh)
{
    const size_t node = LEAF_S + (size_t)blockIdx.x * 4 + (threadIdx.x >> 6);
    const int j = (threadIdx.x & 63) << 2;
    const float4 i4 = *(const float4*)&xiou[node * 768 + j];
    const float4 o4 = *(const float4*)&xiou[node * 768 + 256 + j];
    const float4 u4 = *(const float4*)&xiou[node * 768 + 512 + j];
    float4 c, h;
    c.x = sigm(i4.x) * tanhf(u4.x); h.x = sigm(o4.x) * tanhf(c.x);
    c.y = sigm(i4.y) * tanhf(u4.y); h.y = sigm(o4.y) * tanhf(c.y);
    c.z = sigm(i4.z) * tanhf(u4.z); h.z = sigm(o4.z) * tanhf(c.z);
    c.w = sigm(i4.w) * tanhf(u4.w); h.w = sigm(o4.w) * tanhf(c.w);
    *(float4*)&h_out[node * 256 + j] = h;
    *(float4*)&c_out[node * 256 + j] = c;
    uint2 p;
    p.x = packh(__float2half_rn(h.x), __float2half_rn(h.y));
    p.y = packh(__float2half_rn(h.z), __float2half_rn(h.w));
    *(uint2*)&hh[node * 256 + j] = p;
}

__global__ void combine_kernel(const float* __restrict__ xiou,
                               const float* __restrict__ xfq,
                               const __half* __restrict__ hu,
                               float* __restrict__ h_out,
                               float* __restrict__ c_out,
                               __half* __restrict__ hh,
                               int s0, int child_start)
{
    const int i = blockIdx.x;
    const int j = threadIdx.x;
    const size_t gr = (size_t)(s0 + i);

    const float ig = xiou[gr * 768 + j]       + __half2float(hu[(size_t)i * 1024 + j]);
    const float og = xiou[gr * 768 + 256 + j] + __half2float(hu[(size_t)i * 1024 + 256 + j]);
    const float ug = xiou[gr * 768 + 512 + j] + __half2float(hu[(size_t)i * 1024 + 512 + j]);
    const float f  = sigm(xfq[gr * 512 + j]   + __half2float(hu[(size_t)i * 1024 + 768 + j]));

    const size_t cb = (size_t)(child_start + i * 4) * 256 + j;
    const float csum = c_out[cb] + c_out[cb + 256] + c_out[cb + 512] + c_out[cb + 768];

    const float c = sigm(ig) * tanhf(ug) + f * csum;
    const float h = sigm(og) * tanhf(c);
    h_out[gr * 256 + j] = h;
    c_out[gr * 256 + j] = c;
    hh[gr * 256 + j] = __float2half_rn(h);
}

// ---------------------------------------------------------------------------
// Fused small-level kernel (n <= 64): one CTA = 2 nodes, all phases fp32.
// ---------------------------------------------------------------------------
__global__ void __launch_bounds__(512, 1)
fused_level(const float* __restrict__ xiou,
            const float* __restrict__ xfq,
            const float* __restrict__ Wk,  const float* __restrict__ bk_,
            const float* __restrict__ Wv,  const float* __restrict__ bv_,
            const float* __restrict__ Wl,  const float* __restrict__ bl_,
            const float* __restrict__ Uiou_w, const float* __restrict__ Uiou_b,
            const float* __restrict__ Uf_w,   const float* __restrict__ Uf_b,
            float* __restrict__ h_out, float* __restrict__ c_out,
            int s0, int cs, int n)
{
    __shared__ float chs[8][256];
    __shared__ float kvs[8][512];
    __shared__ float atts[2][256];
    __shared__ float hatts[2][256];
    __shared__ float hus[2][1024];

    const int tid = threadIdx.x;
    const int node0 = blockIdx.x * 2;
    const int nn = (n - node0) < 2 ? (n - node0) : 2;

    for (int idx = tid; idx < 4 * nn * 256; idx += 512) {
        int r = idx >> 8, k = idx & 255;
        chs[r][k] = h_out[(size_t)(cs + node0 * 4 + r) * 256 + k];
    }
    __syncthreads();

    {
        int c = tid;
        const float* W = (c < 256) ? (Wk + c) : (Wv + (c - 256));
        float acc[8] = {0, 0, 0, 0, 0, 0, 0, 0};
        int rmax = 4 * nn;
        #pragma unroll 4
        for (int k = 0; k < 256; k++) {
            float w = W[(size_t)k * 256];
            #pragma unroll
            for (int r = 0; r < 8; r++)
                acc[r] += chs[r][k] * w;
        }
        float b = (c < 256) ? bk_[c] : bv_[c - 256];
        for (int r = 0; r < rmax; r++) kvs[r][c] = acc[r] + b;
    }
    __syncthreads();

    {
        int i = tid >> 8, d = tid & 255;
        if (i < nn) {
            float qv = xfq[(size_t)(s0 + node0 + i) * 512 + 256 + d];
            float logit[4];
            #pragma unroll
            for (int k = 0; k < 4; k++) {
                float p = qv * kvs[i * 4 + k][d];
                #pragma unroll
                for (int off = 16; off > 0; off >>= 1)
                    p += __shfl_xor_sync(0xffffffffu, p, off);
                logit[k] = p * 0.1767766952966369f;
            }
            float mx = fmaxf(fmaxf(logit[0], logit[1]), fmaxf(logit[2], logit[3]));
            float e[4], s = 0.f;
            #pragma unroll
            for (int k = 0; k < 4; k++) { e[k] = expf(logit[k] - mx); s += e[k]; }
            float inv = 1.f / s;
            float o = 0.f;
            #pragma unroll
            for (int k = 0; k < 4; k++)
                o += (e[k] * inv) * kvs[i * 4 + k][256 + d];
            atts[i][d] = o;
        }
    }
    __syncthreads();

    if (tid < 256) {
        int c = tid;
        float a0 = 0.f, a1 = 0.f;
        #pragma unroll 4
        for (int k = 0; k < 256; k++) {
            float w = Wl[(size_t)k * 256 + c];
            a0 += atts[0][k] * w;
            a1 += atts[1][k] * w;
        }
        hatts[0][c] = a0 + bl_[c];
        hatts[1][c] = a1 + bl_[c];
    }
    __syncthreads();

    #pragma unroll
    for (int pass = 0; pass < 2; pass++) {
        int cc = tid + pass * 512;
        float a0 = 0.f, a1 = 0.f, b;
        if (cc < 768) {
            #pragma unroll 4
            for (int k = 0; k < 256; k++) {
                float w = Uiou_w[(size_t)k * 768 + cc];
                a0 += hatts[0][k] * w;
                a1 += hatts[1][k] * w;
            }
            b = Uiou_b[cc];
        } else {
            int c2 = cc - 768;
            #pragma unroll 4
            for (int k = 0; k < 256; k++) {
                float w = Uf_w[(size_t)k * 256 + c2];
                a0 += hatts[0][k] * w;
                a1 += hatts[1][k] * w;
            }
            b = Uf_b[c2];
        }
        hus[0][cc] = a0 + b;
        hus[1][cc] = a1 + b;
    }
    __syncthreads();

    {
        int i = tid >> 8, j = tid & 255;
        if (i < nn) {
            size_t g = (size_t)(s0 + node0 + i);
            float ig = xiou[g * 768 + j]       + hus[i][j];
            float og = xiou[g * 768 + 256 + j] + hus[i][256 + j];
            float ug = xiou[g * 768 + 512 + j] + hus[i][512 + j];
            float f  = sigm(xfq[g * 512 + j]   + hus[i][768 + j]);
            size_t cb = (size_t)(cs + (node0 + i) * 4) * 256 + j;
            float csum = c_out[cb] + c_out[cb + 256] + c_out[cb + 512] + c_out[cb + 768];
            float cv = sigm(ig) * tanhf(ug) + f * csum;
            float hv = sigm(og) * tanhf(cv);
            h_out[g * 256 + j] = hv;
            c_out[g * 256 + j] = cv;
        }
    }
}

// ---------------------------------------------------------------------------
// Launch
// ---------------------------------------------------------------------------
extern "C" void kernel_launch(void* const* d_in, const int* in_sizes, int n_in,
                              void* d_out, int out_size)
{
    const float* x      = (const float*)d_in[0];
    const float* W_iou  = (const float*)d_in[1];
    const float* b_iou  = (const float*)d_in[2];
    const float* W_f    = (const float*)d_in[3];
    const float* b_f    = (const float*)d_in[4];
    const float* Wq     = (const float*)d_in[5];
    const float* bq     = (const float*)d_in[6];
    const float* Wk     = (const float*)d_in[7];
    const float* bk     = (const float*)d_in[8];
    const float* Wv     = (const float*)d_in[9];
    const float* bv     = (const float*)d_in[10];
    const float* Wl     = (const float*)d_in[11];
    const float* bl     = (const float*)d_in[12];
    const float* Uiou_w = (const float*)d_in[13];
    const float* Uiou_b = (const float*)d_in[14];
    const float* Uf_w   = (const float*)d_in[15];
    const float* Uf_b   = (const float*)d_in[16];

    float* h_out = (float*)d_out;
    float* c_out = h_out + (size_t)NN * 256;

    float *xiou, *xfq, *bias;
    __half *hu, *kkvv, *att, *hatt, *xh, *hh, *wthi;
    cudaGetSymbolAddress((void**)&xiou, g_xiou);
    cudaGetSymbolAddress((void**)&xfq,  g_xfq);
    cudaGetSymbolAddress((void**)&hu,   g_hu);
    cudaGetSymbolAddress((void**)&bias, g_bias);
    cudaGetSymbolAddress((void**)&kkvv, g_kkvv);
    cudaGetSymbolAddress((void**)&att,  g_att);
    cudaGetSymbolAddress((void**)&hatt, g_hatt);
    cudaGetSymbolAddress((void**)&xh,   g_xh);
    cudaGetSymbolAddress((void**)&hh,   g_hh);
    cudaGetSymbolAddress((void**)&wthi, g_wthi);

    cudaFuncSetAttribute(gemm_f16, cudaFuncAttributeMaxDynamicSharedMemorySize, GSMEM);

    auto GEMM = [&](const __half* A, int wt, float* C, __half* Ch, int M, int Ntot) {
        dim3 grid((M + 127) / 128, Ntot / 128);
        gemm_f16<<<grid, 256, GSMEM>>>(A, wthi + (size_t)wt * 256,
                                       bias + wt, C, Ch, M, Ntot);
    };

    // ---- combined weight prep (1 launch) ----
    PrepArgs pa;
    pa.W[0] = W_iou;  pa.N[0] = 768; pa.row_off[0] = WT_IOU;
    pa.W[1] = W_f;    pa.N[1] = 256; pa.row_off[1] = WT_FQ;
    pa.W[2] = Wq;     pa.N[2] = 256; pa.row_off[2] = WT_FQ + 256;
    pa.W[3] = Wk;     pa.N[3] = 256; pa.row_off[3] = WT_KV;
    pa.W[4] = Wv;     pa.N[4] = 256; pa.row_off[4] = WT_KV + 256;
    pa.W[5] = Wl;     pa.N[5] = 256; pa.row_off[5] = WT_L;
    pa.W[6] = Uiou_w; pa.N[6] = 768; pa.row_off[6] = WT_U;
    pa.W[7] = Uf_w;   pa.N[7] = 256; pa.row_off[7] = WT_U + 768;
    pa.blk_cum[0] = 0;
    for (int m = 0; m < 8; m++) pa.blk_cum[m + 1] = pa.blk_cum[m] + pa.N[m] / 32;
    prep_all<<<pa.blk_cum[8], 256>>>(pa, wthi);

    // ---- bias concat ----
    cudaMemcpyAsync(bias + WT_IOU,      b_iou,  768 * 4, cudaMemcpyDeviceToDevice, 0);
    cudaMemcpyAsync(bias + WT_FQ,       b_f,    256 * 4, cudaMemcpyDeviceToDevice, 0);
    cudaMemcpyAsync(bias + WT_FQ + 256, bq,     256 * 4, cudaMemcpyDeviceToDevice, 0);
    cudaMemcpyAsync(bias + WT_KV,       bk,     256 * 4, cudaMemcpyDeviceToDevice, 0);
    cudaMemcpyAsync(bias + WT_KV + 256, bv,     256 * 4, cudaMemcpyDeviceToDevice, 0);
    cudaMemcpyAsync(bias + WT_L,        bl,     256 * 4, cudaMemcpyDeviceToDevice, 0);
    cudaMemcpyAsync(bias + WT_U,        Uiou_b, 768 * 4, cudaMemcpyDeviceToDevice, 0);
    cudaMemcpyAsync(bias + WT_U + 768,  Uf_b,   256 * 4, cudaMemcpyDeviceToDevice, 0);

    // ---- split x, precompute GEMMs ----
    const int tot4 = NN * 256 / 4;
    split_x<<<(tot4 + 255) / 256, 256>>>(x, xh, tot4);
    GEMM(xh, WT_IOU, xiou, nullptr, NN, 768);
    GEMM(xh, WT_FQ,  xfq,  nullptr, NI, 512);

    // ---- leaf level ----
    leaf_kernel<<<LEAF_N / 4, 256>>>(xiou, h_out, c_out, hh);

    // ---- internal levels, bottom-up ----
    const int starts[9] = {0, 1, 5, 21, 85, 341, 1365, 5461, 21845};
    for (int l = 7; l >= 4; l--) {
        const int n  = 1 << (2 * l);
        const int s0 = starts[l];
        const int cs = starts[l + 1];
        const int nK = n * 4;
        const __half* chh = hh + (size_t)cs * 256;

        GEMM(chh, WT_KV, nullptr, kkvv, nK, 512);
        attn_kernel<<<n, 256>>>(xfq, kkvv, att, s0);
        GEMM(att, WT_L, nullptr, hatt, n, 256);
        GEMM(hatt, WT_U, nullptr, hu, n, 1024);
        combine_kernel<<<n, 256>>>(xiou, xfq, hu, h_out, c_out, hh, s0, cs);
    }
    for (int l = 3; l >= 0; l--) {
        const int n  = 1 << (2 * l);
        fused_level<<<(n + 1) / 2, 512>>>(xiou, xfq,
                                          Wk, bk, Wv, bv, Wl, bl,
                                          Uiou_w, Uiou_b, Uf_w, Uf_b,
                                          h_out, c_out,
                                          starts[l], starts[l + 1], n);
    }
}

// round 9
// speedup vs baseline: 1.3786x; 1.0797x over previous
#include <cuda_runtime.h>
#include <cuda_fp16.h>
#include <math.h>
#include <stdint.h>

// ---------------------------------------------------------------------------
// Problem constants
// ---------------------------------------------------------------------------
#define NN        87381     // total nodes = (4^9-1)/3
#define NI        21845     // internal nodes
#define LEAF_N    65536
#define LEAF_S    21845

// ---------------------------------------------------------------------------
// Device scratch (static — no allocation allowed)
// ---------------------------------------------------------------------------
__device__ __half g_xiou[NN * 768];          // iou preactivations (fp16)
__device__ __half g_xfq[NI * 512];           // cols 0-255: x_f, 256-511: q
__device__ __half g_hu[16384 * 1024];        // cols 0-767: h_iou, 768-1023: h_f
__device__ __half g_kkvv[65536 * 512];       // cols 0-255: k, 256-511: v
__device__ __half g_att[16384 * 256];
__device__ __half g_hatt[16384 * 256];
__device__ __half g_xh[NN * 256];            // x as fp16
__device__ __half g_hh[NN * 256];            // h as fp16

// weight rows (transposed fp16). row index == bias index.
#define WT_IOU  0       // 768 rows
#define WT_FQ   768     // 512 rows (f, q)
#define WT_KV   1280    // 512 rows (k, v)
#define WT_L    1792    // 256 rows
#define WT_U    2048    // 1024 rows (uiou, uf)
__device__ __half g_wthi[3072 * 256];
__device__ float  g_bias[3072];

// ---------------------------------------------------------------------------
// PTX helpers (sm_80+ — safe for plain sm_103 ptxas target)
// ---------------------------------------------------------------------------
__device__ __forceinline__ uint32_t s2u(const void* p) {
    uint32_t a;
    asm("{ .reg .u64 t; cvta.to.shared.u64 t, %1; cvt.u32.u64 %0, t; }"
        : "=r"(a) : "l"(p));
    return a;
}
__device__ __forceinline__ void cpa16(uint32_t dst, const void* src, int nbytes) {
    asm volatile("cp.async.cg.shared.global [%0], [%1], 16, %2;"
                 :: "r"(dst), "l"(src), "r"(nbytes) : "memory");
}
__device__ __forceinline__ void cpa_commit() {
    asm volatile("cp.async.commit_group;" ::: "memory");
}
__device__ __forceinline__ void ldm4(uint32_t* r, uint32_t addr) {
    asm volatile("ldmatrix.sync.aligned.m8n8.x4.shared.b16 {%0,%1,%2,%3}, [%4];"
                 : "=r"(r[0]), "=r"(r[1]), "=r"(r[2]), "=r"(r[3]) : "r"(addr));
}
__device__ __forceinline__ void mma16816(float* c, const uint32_t* a, const uint32_t* b) {
    asm volatile(
        "mma.sync.aligned.m16n8k16.row.col.f32.f16.f16.f32 "
        "{%0,%1,%2,%3}, {%4,%5,%6,%7}, {%8,%9}, {%0,%1,%2,%3};"
        : "+f"(c[0]), "+f"(c[1]), "+f"(c[2]), "+f"(c[3])
        : "r"(a[0]), "r"(a[1]), "r"(a[2]), "r"(a[3]), "r"(b[0]), "r"(b[1]));
}
__device__ __forceinline__ uint32_t swadr(uint32_t base, int row, int gran) {
    return base + row * 128 + ((gran ^ (row & 7)) << 4);
}
__device__ __forceinline__ uint32_t packh(__half a, __half b) {
    return ((uint32_t)__half_as_ushort(b) << 16) | __half_as_ushort(a);
}
__device__ __forceinline__ float sigm(float x) { return 1.f / (1.f + expf(-x)); }

// ---------------------------------------------------------------------------
// fp16 HMMA GEMM:  Ch[M, Ntot] = fp16( A[M,256] @ Wt^T + bias )
//   CTA tile 128x128, 8 warps (2m x 4n), warp 64x32, k-chunk 64 x4,
//   2-stage cp.async pipeline, 64KB smem -> 2 CTAs/SM.
// ---------------------------------------------------------------------------
#define STG    32768
#define OA     0
#define OBH    16384
#define GSMEM  (2 * STG)   // 65536 bytes

__global__ void __launch_bounds__(256, 2)
gemm_f16(const __half* __restrict__ A,
         const __half* __restrict__ Bhi,
         const float* __restrict__ bias,
         __half* __restrict__ Ch,
         int M, int Ntot)
{
    extern __shared__ char smem[];
    const uint32_t sb = s2u(smem);
    const int tid  = threadIdx.x;
    const int lane = tid & 31;
    const int wid  = tid >> 5;
    const int wm   = wid & 1;
    const int wn   = wid >> 1;
    const int bm   = blockIdx.x * 128;
    const int n0   = blockIdx.y * 128;

    float acc[4][4][4];
    #pragma unroll
    for (int a = 0; a < 4; a++)
        #pragma unroll
        for (int b = 0; b < 4; b++)
            #pragma unroll
            for (int c = 0; c < 4; c++) acc[a][b][c] = 0.f;

    auto stage_chunk = [&](int kc) {
        uint32_t sa = sb + (kc & 1) * STG;
        #pragma unroll
        for (int t = 0; t < 4; t++) {
            int i = tid + t * 256;
            int row = i >> 3, g = i & 7;
            uint32_t d = row * 128 + ((g ^ (row & 7)) << 4);
            int  arow = bm + row;
            int  av   = arow < M ? 16 : 0;
            size_t as = (size_t)(arow < M ? arow : 0) * 256 + kc * 64 + g * 8;
            size_t bs = (size_t)(n0 + row) * 256 + kc * 64 + g * 8;
            cpa16(sa + OA  + d, A + as, av);
            cpa16(sa + OBH + d, Bhi + bs, 16);
        }
        cpa_commit();
    };

    stage_chunk(0);

    for (int kc = 0; kc < 4; kc++) {
        if (kc < 3) {
            stage_chunk(kc + 1);
            asm volatile("cp.async.wait_group 1;" ::: "memory");
        } else {
            asm volatile("cp.async.wait_group 0;" ::: "memory");
        }
        __syncthreads();

        const uint32_t sa = sb + (kc & 1) * STG;
        #pragma unroll
        for (int ks = 0; ks < 4; ks++) {
            uint32_t af[4][4], bh[2][4];
            #pragma unroll
            for (int mi = 0; mi < 4; mi++) {
                int rA = wm * 64 + mi * 16 + (lane & 15);
                int gA = 2 * ks + (lane >> 4);
                ldm4(af[mi], swadr(sa + OA, rA, gA));
            }
            #pragma unroll
            for (int bi = 0; bi < 2; bi++) {
                int rB = wn * 32 + bi * 16 + (lane & 7) + ((lane >> 4) << 3);
                int gB = 2 * ks + ((lane >> 3) & 1);
                ldm4(bh[bi], swadr(sa + OBH, rB, gB));
            }
            #pragma unroll
            for (int mi = 0; mi < 4; mi++)
                #pragma unroll
                for (int nf = 0; nf < 4; nf++)
                    mma16816(acc[mi][nf], af[mi], &bh[nf >> 1][(nf & 1) * 2]);
        }
        __syncthreads();
    }

    #pragma unroll
    for (int mi = 0; mi < 4; mi++) {
        #pragma unroll
        for (int nf = 0; nf < 4; nf++) {
            int r0  = bm + wm * 64 + mi * 16 + (lane >> 2);
            int col = n0 + wn * 32 + nf * 8 + ((lane & 3) << 1);
            float2 b2 = *(const float2*)&bias[col];
            if (r0 < M) {
                size_t o = (size_t)r0 * Ntot + col;
                *(uint32_t*)&Ch[o] = packh(__float2half_rn(acc[mi][nf][0] + b2.x),
                                           __float2half_rn(acc[mi][nf][1] + b2.y));
            }
            if (r0 + 8 < M) {
                size_t o = (size_t)(r0 + 8) * Ntot + col;
                *(uint32_t*)&Ch[o] = packh(__float2half_rn(acc[mi][nf][2] + b2.x),
                                           __float2half_rn(acc[mi][nf][3] + b2.y));
            }
        }
    }
}

// ---------------------------------------------------------------------------
// Combined weight prep: one launch transposes all 8 matrices -> fp16 rows.
// ---------------------------------------------------------------------------
struct PrepArgs {
    const float* W[8];
    int N[8];
    int row_off[8];
    int blk_cum[9];
};

__global__ void prep_all(PrepArgs pa, __half* __restrict__ wthi)
{
    __shared__ float tile[256][33];
    int b = blockIdx.x;
    int m = 0;
    while (b >= pa.blk_cum[m + 1]) m++;
    const int n0 = (b - pa.blk_cum[m]) * 32;
    const float* W = pa.W[m];
    const int N = pa.N[m];
    __half* out = wthi + (size_t)pa.row_off[m] * 256;

    const int tx = threadIdx.x & 31;
    const int ty = threadIdx.x >> 5;
    for (int k = ty; k < 256; k += 8)
        tile[k][tx] = W[(size_t)k * N + n0 + tx];
    __syncthreads();
    for (int nr = ty * 4; nr < ty * 4 + 4; nr++)
        for (int k = tx; k < 256; k += 32)
            out[(size_t)(n0 + nr) * 256 + k] = __float2half_rn(tile[k][nr]);
}

__global__ void split_x(const float* __restrict__ x,
                        __half* __restrict__ xh, int total4)
{
    int i = blockIdx.x * blockDim.x + threadIdx.x;
    if (i >= total4) return;
    float4 v = *(const float4*)&x[i * 4];
    uint2 p;
    p.x = packh(__float2half_rn(v.x), __float2half_rn(v.y));
    p.y = packh(__float2half_rn(v.z), __float2half_rn(v.w));
    *(uint2*)&xh[i * 4] = p;
}

// ---------------------------------------------------------------------------
// Attention: one block per node, warp per head
// ---------------------------------------------------------------------------
__global__ void attn_kernel(const __half* __restrict__ xfq,
                            const __half* __restrict__ kkvv,
                            __half* __restrict__ out,
                            int s0)
{
    const int node = blockIdx.x;
    const int d = threadIdx.x;
    const float qv = __half2float(xfq[(size_t)(s0 + node) * 512 + 256 + d]);

    float logit[4];
    #pragma unroll
    for (int k = 0; k < 4; k++) {
        float p = qv * __half2float(kkvv[((size_t)(node * 4 + k)) * 512 + d]);
        #pragma unroll
        for (int off = 16; off > 0; off >>= 1)
            p += __shfl_xor_sync(0xffffffffu, p, off);
        logit[k] = p * 0.1767766952966369f;
    }
    float mx = fmaxf(fmaxf(logit[0], logit[1]), fmaxf(logit[2], logit[3]));
    float e[4], s = 0.f;
    #pragma unroll
    for (int k = 0; k < 4; k++) { e[k] = expf(logit[k] - mx); s += e[k]; }
    const float inv = 1.f / s;

    float o = 0.f;
    #pragma unroll
    for (int k = 0; k < 4; k++)
        o += (e[k] * inv) * __half2float(kkvv[((size_t)(node * 4 + k)) * 512 + 256 + d]);
    out[(size_t)node * 256 + d] = __float2half_rn(o);
}

// ---------------------------------------------------------------------------
// Elementwise
// ---------------------------------------------------------------------------
__device__ __forceinline__ float h2f(const __half h) { return __half2float(h); }

__global__ void leaf_kernel(const __half* __restrict__ xiou,
                            float* __restrict__ h_out,
                            float* __restrict__ c_out,
                            __half* __restrict__ hh)
{
    const size_t node = LEAF_S + (size_t)blockIdx.x * 4 + (threadIdx.x >> 6);
    const int j = (threadIdx.x & 63) << 2;
    const __half2* pi = (const __half2*)&xiou[node * 768 + j];
    const __half2* po = (const __half2*)&xiou[node * 768 + 256 + j];
    const __half2* pu = (const __half2*)&xiou[node * 768 + 512 + j];
    float2 ia = __half22float2(pi[0]), ib = __half22float2(pi[1]);
    float2 oa = __half22float2(po[0]), ob = __half22float2(po[1]);
    float2 ua = __half22float2(pu[0]), ub = __half22float2(pu[1]);
    float4 c, h;
    c.x = sigm(ia.x) * tanhf(ua.x); h.x = sigm(oa.x) * tanhf(c.x);
    c.y = sigm(ia.y) * tanhf(ua.y); h.y = sigm(oa.y) * tanhf(c.y);
    c.z = sigm(ib.x) * tanhf(ub.x); h.z = sigm(ob.x) * tanhf(c.z);
    c.w = sigm(ib.y) * tanhf(ub.y); h.w = sigm(ob.y) * tanhf(c.w);
    *(float4*)&h_out[node * 256 + j] = h;
    *(float4*)&c_out[node * 256 + j] = c;
    uint2 p;
    p.x = packh(__float2half_rn(h.x), __float2half_rn(h.y));
    p.y = packh(__float2half_rn(h.z), __float2half_rn(h.w));
    *(uint2*)&hh[node * 256 + j] = p;
}

__global__ void combine_kernel(const __half* __restrict__ xiou,
                               const __half* __restrict__ xfq,
                               const __half* __restrict__ hu,
                               float* __restrict__ h_out,
                               float* __restrict__ c_out,
                               __half* __restrict__ hh,
                               int s0, int child_start)
{
    const int i = blockIdx.x;
    const int j = threadIdx.x;
    const size_t gr = (size_t)(s0 + i);

    const float ig = h2f(xiou[gr * 768 + j])       + h2f(hu[(size_t)i * 1024 + j]);
    const float og = h2f(xiou[gr * 768 + 256 + j]) + h2f(hu[(size_t)i * 1024 + 256 + j]);
    const float ug = h2f(xiou[gr * 768 + 512 + j]) + h2f(hu[(size_t)i * 1024 + 512 + j]);
    const float f  = sigm(h2f(xfq[gr * 512 + j])   + h2f(hu[(size_t)i * 1024 + 768 + j]));

    const size_t cb = (size_t)(child_start + i * 4) * 256 + j;
    const float csum = c_out[cb] + c_out[cb + 256] + c_out[cb + 512] + c_out[cb + 768];

    const float c = sigm(ig) * tanhf(ug) + f * csum;
    const float h = sigm(og) * tanhf(c);
    h_out[gr * 256 + j] = h;
    c_out[gr * 256 + j] = c;
    hh[gr * 256 + j] = __float2half_rn(h);
}

// ---------------------------------------------------------------------------
// Fused small-level kernel (n <= 64): one CTA = 2 nodes, all phases fp32.
// ---------------------------------------------------------------------------
__global__ void __launch_bounds__(512, 1)
fused_level(const __half* __restrict__ xiou,
            const __half* __restrict__ xfq,
            const float* __restrict__ Wk,  const float* __restrict__ bk_,
            const float* __restrict__ Wv,  const float* __restrict__ bv_,
            const float* __restrict__ Wl,  const float* __restrict__ bl_,
            const float* __restrict__ Uiou_w, const float* __restrict__ Uiou_b,
            const float* __restrict__ Uf_w,   const float* __restrict__ Uf_b,
            float* __restrict__ h_out, float* __restrict__ c_out,
            int s0, int cs, int n)
{
    __shared__ float chs[8][256];
    __shared__ float kvs[8][512];
    __shared__ float atts[2][256];
    __shared__ float hatts[2][256];
    __shared__ float hus[2][1024];

    const int tid = threadIdx.x;
    const int node0 = blockIdx.x * 2;
    const int nn = (n - node0) < 2 ? (n - node0) : 2;

    for (int idx = tid; idx < 4 * nn * 256; idx += 512) {
        int r = idx >> 8, k = idx & 255;
        chs[r][k] = h_out[(size_t)(cs + node0 * 4 + r) * 256 + k];
    }
    __syncthreads();

    {
        int c = tid;
        const float* W = (c < 256) ? (Wk + c) : (Wv + (c - 256));
        float acc[8] = {0, 0, 0, 0, 0, 0, 0, 0};
        int rmax = 4 * nn;
        #pragma unroll 4
        for (int k = 0; k < 256; k++) {
            float w = W[(size_t)k * 256];
            #pragma unroll
            for (int r = 0; r < 8; r++)
                acc[r] += chs[r][k] * w;
        }
        float b = (c < 256) ? bk_[c] : bv_[c - 256];
        for (int r = 0; r < rmax; r++) kvs[r][c] = acc[r] + b;
    }
    __syncthreads();

    {
        int i = tid >> 8, d = tid & 255;
        if (i < nn) {
            float qv = h2f(xfq[(size_t)(s0 + node0 + i) * 512 + 256 + d]);
            float logit[4];
            #pragma unroll
            for (int k = 0; k < 4; k++) {
                float p = qv * kvs[i * 4 + k][d];
                #pragma unroll
                for (int off = 16; off > 0; off >>= 1)
                    p += __shfl_xor_sync(0xffffffffu, p, off);
                logit[k] = p * 0.1767766952966369f;
            }
            float mx = fmaxf(fmaxf(logit[0], logit[1]), fmaxf(logit[2], logit[3]));
            float e[4], s = 0.f;
            #pragma unroll
            for (int k = 0; k < 4; k++) { e[k] = expf(logit[k] - mx); s += e[k]; }
            float inv = 1.f / s;
            float o = 0.f;
            #pragma unroll
            for (int k = 0; k < 4; k++)
                o += (e[k] * inv) * kvs[i * 4 + k][256 + d];
            atts[i][d] = o;
        }
    }
    __syncthreads();

    if (tid < 256) {
        int c = tid;
        float a0 = 0.f, a1 = 0.f;
        #pragma unroll 4
        for (int k = 0; k < 256; k++) {
            float w = Wl[(size_t)k * 256 + c];
            a0 += atts[0][k] * w;
            a1 += atts[1][k] * w;
        }
        hatts[0][c] = a0 + bl_[c];
        hatts[1][c] = a1 + bl_[c];
    }
    __syncthreads();

    #pragma unroll
    for (int pass = 0; pass < 2; pass++) {
        int cc = tid + pass * 512;
        float a0 = 0.f, a1 = 0.f, b;
        if (cc < 768) {
            #pragma unroll 4
            for (int k = 0; k < 256; k++) {
                float w = Uiou_w[(size_t)k * 768 + cc];
                a0 += hatts[0][k] * w;
                a1 += hatts[1][k] * w;
            }
            b = Uiou_b[cc];
        } else {
            int c2 = cc - 768;
            #pragma unroll 4
            for (int k = 0; k < 256; k++) {
                float w = Uf_w[(size_t)k * 256 + c2];
                a0 += hatts[0][k] * w;
                a1 += hatts[1][k] * w;
            }
            b = Uf_b[c2];
        }
        hus[0][cc] = a0 + b;
        hus[1][cc] = a1 + b;
    }
    __syncthreads();

    {
        int i = tid >> 8, j = tid & 255;
        if (i < nn) {
            size_t g = (size_t)(s0 + node0 + i);
            float ig = h2f(xiou[g * 768 + j])       + hus[i][j];
            float og = h2f(xiou[g * 768 + 256 + j]) + hus[i][256 + j];
            float ug = h2f(xiou[g * 768 + 512 + j]) + hus[i][512 + j];
            float f  = sigm(h2f(xfq[g * 512 + j])   + hus[i][768 + j]);
            size_t cb = (size_t)(cs + (node0 + i) * 4) * 256 + j;
            float csum = c_out[cb] + c_out[cb + 256] + c_out[cb + 512] + c_out[cb + 768];
            float cv = sigm(ig) * tanhf(ug) + f * csum;
            float hv = sigm(og) * tanhf(cv);
            h_out[g * 256 + j] = hv;
            c_out[g * 256 + j] = cv;
        }
    }
}

// ---------------------------------------------------------------------------
// Launch
// ---------------------------------------------------------------------------
extern "C" void kernel_launch(void* const* d_in, const int* in_sizes, int n_in,
                              void* d_out, int out_size)
{
    const float* x      = (const float*)d_in[0];
    const float* W_iou  = (const float*)d_in[1];
    const float* b_iou  = (const float*)d_in[2];
    const float* W_f    = (const float*)d_in[3];
    const float* b_f    = (const float*)d_in[4];
    const float* Wq     = (const float*)d_in[5];
    const float* bq     = (const float*)d_in[6];
    const float* Wk     = (const float*)d_in[7];
    const float* bk     = (const float*)d_in[8];
    const float* Wv     = (const float*)d_in[9];
    const float* bv     = (const float*)d_in[10];
    const float* Wl     = (const float*)d_in[11];
    const float* bl     = (const float*)d_in[12];
    const float* Uiou_w = (const float*)d_in[13];
    const float* Uiou_b = (const float*)d_in[14];
    const float* Uf_w   = (const float*)d_in[15];
    const float* Uf_b   = (const float*)d_in[16];

    float* h_out = (float*)d_out;
    float* c_out = h_out + (size_t)NN * 256;

    float *bias;
    __half *xiou, *xfq, *hu, *kkvv, *att, *hatt, *xh, *hh, *wthi;
    cudaGetSymbolAddress((void**)&xiou, g_xiou);
    cudaGetSymbolAddress((void**)&xfq,  g_xfq);
    cudaGetSymbolAddress((void**)&hu,   g_hu);
    cudaGetSymbolAddress((void**)&bias, g_bias);
    cudaGetSymbolAddress((void**)&kkvv, g_kkvv);
    cudaGetSymbolAddress((void**)&att,  g_att);
    cudaGetSymbolAddress((void**)&hatt, g_hatt);
    cudaGetSymbolAddress((void**)&xh,   g_xh);
    cudaGetSymbolAddress((void**)&hh,   g_hh);
    cudaGetSymbolAddress((void**)&wthi, g_wthi);

    cudaFuncSetAttribute(gemm_f16, cudaFuncAttributeMaxDynamicSharedMemorySize, GSMEM);

    auto GEMM = [&](const __half* A, int wt, __half* Ch, int M, int Ntot) {
        dim3 grid((M + 127) / 128, Ntot / 128);
        gemm_f16<<<grid, 256, GSMEM>>>(A, wthi + (size_t)wt * 256,
                                       bias + wt, Ch, M, Ntot);
    };

    // ---- combined weight prep (1 launch) ----
    PrepArgs pa;
    pa.W[0] = W_iou;  pa.N[0] = 768; pa.row_off[0] = WT_IOU;
    pa.W[1] = W_f;    pa.N[1] = 256; pa.row_off[1] = WT_FQ;
    pa.W[2] = Wq;     pa.N[2] = 256; pa.row_off[2] = WT_FQ + 256;
    pa.W[3] = Wk;     pa.N[3] = 256; pa.row_off[3] = WT_KV;
    pa.W[4] = Wv;     pa.N[4] = 256; pa.row_off[4] = WT_KV + 256;
    pa.W[5] = Wl;     pa.N[5] = 256; pa.row_off[5] = WT_L;
    pa.W[6] = Uiou_w; pa.N[6] = 768; pa.row_off[6] = WT_U;
    pa.W[7] = Uf_w;   pa.N[7] = 256; pa.row_off[7] = WT_U + 768;
    pa.blk_cum[0] = 0;
    for (int m = 0; m < 8; m++) pa.blk_cum[m + 1] = pa.blk_cum[m] + pa.N[m] / 32;
    prep_all<<<pa.blk_cum[8], 256>>>(pa, wthi);

    // ---- bias concat ----
    cudaMemcpyAsync(bias + WT_IOU,      b_iou,  768 * 4, cudaMemcpyDeviceToDevice, 0);
    cudaMemcpyAsync(bias + WT_FQ,       b_f,    256 * 4, cudaMemcpyDeviceToDevice, 0);
    cudaMemcpyAsync(bias + WT_FQ + 256, bq,     256 * 4, cudaMemcpyDeviceToDevice, 0);
    cudaMemcpyAsync(bias + WT_KV,       bk,     256 * 4, cudaMemcpyDeviceToDevice, 0);
    cudaMemcpyAsync(bias + WT_KV + 256, bv,     256 * 4, cudaMemcpyDeviceToDevice, 0);
    cudaMemcpyAsync(bias + WT_L,        bl,     256 * 4, cudaMemcpyDeviceToDevice, 0);
    cudaMemcpyAsync(bias + WT_U,        Uiou_b, 768 * 4, cudaMemcpyDeviceToDevice, 0);
    cudaMemcpyAsync(bias + WT_U + 768,  Uf_b,   256 * 4, cudaMemcpyDeviceToDevice, 0);

    // ---- split x, precompute GEMMs ----
    const int tot4 = NN * 256 / 4;
    split_x<<<(tot4 + 255) / 256, 256>>>(x, xh, tot4);
    GEMM(xh, WT_IOU, xiou, NN, 768);
    GEMM(xh, WT_FQ,  xfq,  NI, 512);

    // ---- leaf level ----
    leaf_kernel<<<LEAF_N / 4, 256>>>(xiou, h_out, c_out, hh);

    // ---- internal levels, bottom-up ----
    const int starts[9] = {0, 1, 5, 21, 85, 341, 1365, 5461, 21845};
    for (int l = 7; l >= 4; l--) {
        const int n  = 1 << (2 * l);
        const int s0 = starts[l];
        const int cs = starts[l + 1];
        const int nK = n * 4;
        const __half* chh = hh + (size_t)cs * 256;

        GEMM(chh, WT_KV, kkvv, nK, 512);
        attn_kernel<<<n, 256>>>(xfq, kkvv, att, s0);
        GEMM(att, WT_L, hatt, n, 256);
        GEMM(hatt, WT_U, hu, n, 1024);
        combine_kernel<<<n, 256>>>(xiou, xfq, hu, h_out, c_out, hh, s0, cs);
    }
    for (int l = 3; l >= 0; l--) {
        const int n  = 1 << (2 * l);
        fused_level<<<(n + 1) / 2, 512>>>(xiou, xfq,
                                          Wk, bk, Wv, bv, Wl, bl,
                                          Uiou_w, Uiou_b, Uf_w, Uf_b,
                                          h_out, c_out,
                                          starts[l], starts[l + 1], n);
    }
}

// round 13
// speedup vs baseline: 1.3813x; 1.0020x over previous
#include <cuda_runtime.h>
#include <cuda_fp16.h>
#include <math.h>
#include <stdint.h>

// ---------------------------------------------------------------------------
// Problem constants
// ---------------------------------------------------------------------------
#define NN        87381     // total nodes = (4^9-1)/3
#define NI        21845     // internal nodes
#define LEAF_N    65536
#define LEAF_S    21845

// ---------------------------------------------------------------------------
// Device scratch (static — no allocation allowed)
// ---------------------------------------------------------------------------
__device__ __half g_xiou[NN * 768];          // iou preactivations (fp16)
__device__ __half g_xfq[NI * 512];           // cols 0-255: x_f, 256-511: q
__device__ __half g_hu[16384 * 1024];        // cols 0-767: h_iou, 768-1023: h_f
__device__ __half g_kkvv[65536 * 512];       // cols 0-255: k, 256-511: v
__device__ __half g_att[16384 * 256];
__device__ __half g_hatt[16384 * 256];
__device__ __half g_xh[NN * 256];            // x as fp16
__device__ __half g_hh[NN * 256];            // h as fp16

// weight rows (transposed fp16). row index == bias index.
#define WT_IOU  0       // 768 rows
#define WT_FQ   768     // 512 rows (f, q)
#define WT_KV   1280    // 512 rows (k, v)
#define WT_L    1792    // 256 rows
#define WT_U    2048    // 1024 rows (uiou, uf)
__device__ __half g_wthi[3072 * 256];
__device__ float  g_bias[3072];

// ---------------------------------------------------------------------------
// PTX helpers (sm_80+ — safe for plain sm_103 ptxas target)
// ---------------------------------------------------------------------------
__device__ __forceinline__ uint32_t s2u(const void* p) {
    uint32_t a;
    asm("{ .reg .u64 t; cvta.to.shared.u64 t, %1; cvt.u32.u64 %0, t; }"
        : "=r"(a) : "l"(p));
    return a;
}
__device__ __forceinline__ void cpa16(uint32_t dst, const void* src, int nbytes) {
    asm volatile("cp.async.cg.shared.global [%0], [%1], 16, %2;"
                 :: "r"(dst), "l"(src), "r"(nbytes) : "memory");
}
__device__ __forceinline__ void cpa_commit() {
    asm volatile("cp.async.commit_group;" ::: "memory");
}
__device__ __forceinline__ void ldm4(uint32_t* r, uint32_t addr) {
    asm volatile("ldmatrix.sync.aligned.m8n8.x4.shared.b16 {%0,%1,%2,%3}, [%4];"
                 : "=r"(r[0]), "=r"(r[1]), "=r"(r[2]), "=r"(r[3]) : "r"(addr));
}
__device__ __forceinline__ void mma16816(float* c, const uint32_t* a, const uint32_t* b) {
    asm volatile(
        "mma.sync.aligned.m16n8k16.row.col.f32.f16.f16.f32 "
        "{%0,%1,%2,%3}, {%4,%5,%6,%7}, {%8,%9}, {%0,%1,%2,%3};"
        : "+f"(c[0]), "+f"(c[1]), "+f"(c[2]), "+f"(c[3])
        : "r"(a[0]), "r"(a[1]), "r"(a[2]), "r"(a[3]), "r"(b[0]), "r"(b[1]));
}
__device__ __forceinline__ uint32_t swadr(uint32_t base, int row, int gran) {
    return base + row * 128 + ((gran ^ (row & 7)) << 4);
}
__device__ __forceinline__ uint32_t packh(__half a, __half b) {
    return ((uint32_t)__half_as_ushort(b) << 16) | __half_as_ushort(a);
}
__device__ __forceinline__ float sigm(float x) { return 1.f / (1.f + expf(-x)); }

// ---------------------------------------------------------------------------
// fp16 HMMA GEMM:  Ch[M, Ntot] = fp16( A[M,256] @ Wt^T + bias )
//   CTA tile 128x128, 8 warps (2m x 4n), warp 64x32, k-chunk 64 x4,
//   3-stage cp.async pipeline, ONE barrier per chunk, 96KB smem, 2 CTAs/SM.
// ---------------------------------------------------------------------------
#define STG    32768
#define OA     0
#define OBH    16384
#define GSMEM  (3 * STG)   // 98304 bytes

__global__ void __launch_bounds__(256, 2)
gemm_f16(const __half* __restrict__ A,
         const __half* __restrict__ Bhi,
         const float* __restrict__ bias,
         __half* __restrict__ Ch,
         int M, int Ntot)
{
    extern __shared__ char smem[];
    const uint32_t sb = s2u(smem);
    const int tid  = threadIdx.x;
    const int lane = tid & 31;
    const int wid  = tid >> 5;
    const int wm   = wid & 1;
    const int wn   = wid >> 1;
    const int bm   = blockIdx.x * 128;
    const int n0   = blockIdx.y * 128;

    float acc[4][4][4];
    #pragma unroll
    for (int a = 0; a < 4; a++)
        #pragma unroll
        for (int b = 0; b < 4; b++)
            #pragma unroll
            for (int c = 0; c < 4; c++) acc[a][b][c] = 0.f;

    auto stage_chunk = [&](int kc) {
        uint32_t sa = sb + (kc % 3) * STG;
        #pragma unroll
        for (int t = 0; t < 4; t++) {
            int i = tid + t * 256;
            int row = i >> 3, g = i & 7;
            uint32_t d = row * 128 + ((g ^ (row & 7)) << 4);
            int  arow = bm + row;
            int  av   = arow < M ? 16 : 0;
            size_t as = (size_t)(arow < M ? arow : 0) * 256 + kc * 64 + g * 8;
            size_t bs = (size_t)(n0 + row) * 256 + kc * 64 + g * 8;
            cpa16(sa + OA  + d, A + as, av);
            cpa16(sa + OBH + d, Bhi + bs, 16);
        }
        cpa_commit();
    };

    stage_chunk(0);
    stage_chunk(1);

    for (int kc = 0; kc < 4; kc++) {
        if (kc < 3)
            asm volatile("cp.async.wait_group 1;" ::: "memory");
        else
            asm volatile("cp.async.wait_group 0;" ::: "memory");
        // single barrier per chunk: proves (a) stage kc is loaded for all
        // warps, and (b) all warps finished computing chunk kc-1, whose
        // buffer ((kc-1)%3 == (kc+2)%3) is about to be overwritten.
        __syncthreads();
        if (kc + 2 < 4) stage_chunk(kc + 2);

        const uint32_t sa = sb + (kc % 3) * STG;
        #pragma unroll
        for (int ks = 0; ks < 4; ks++) {
            uint32_t af[4][4], bh[2][4];
            #pragma unroll
            for (int mi = 0; mi < 4; mi++) {
                int rA = wm * 64 + mi * 16 + (lane & 15);
                int gA = 2 * ks + (lane >> 4);
                ldm4(af[mi], swadr(sa + OA, rA, gA));
            }
            #pragma unroll
            for (int bi = 0; bi < 2; bi++) {
                int rB = wn * 32 + bi * 16 + (lane & 7) + ((lane >> 4) << 3);
                int gB = 2 * ks + ((lane >> 3) & 1);
                ldm4(bh[bi], swadr(sa + OBH, rB, gB));
            }
            #pragma unroll
            for (int mi = 0; mi < 4; mi++)
                #pragma unroll
                for (int nf = 0; nf < 4; nf++)
                    mma16816(acc[mi][nf], af[mi], &bh[nf >> 1][(nf & 1) * 2]);
        }
    }

    #pragma unroll
    for (int mi = 0; mi < 4; mi++) {
        #pragma unroll
        for (int nf = 0; nf < 4; nf++) {
            int r0  = bm + wm * 64 + mi * 16 + (lane >> 2);
            int col = n0 + wn * 32 + nf * 8 + ((lane & 3) << 1);
            float2 b2 = *(const float2*)&bias[col];
            if (r0 < M) {
                size_t o = (size_t)r0 * Ntot + col;
                *(uint32_t*)&Ch[o] = packh(__float2half_rn(acc[mi][nf][0] + b2.x),
                                           __float2half_rn(acc[mi][nf][1] + b2.y));
            }
            if (r0 + 8 < M) {
                size_t o = (size_t)(r0 + 8) * Ntot + col;
                *(uint32_t*)&Ch[o] = packh(__float2half_rn(acc[mi][nf][2] + b2.x),
                                           __float2half_rn(acc[mi][nf][3] + b2.y));
            }
        }
    }
}

// ---------------------------------------------------------------------------
// Combined weight prep: one launch transposes all 8 matrices -> fp16 rows.
// ---------------------------------------------------------------------------
struct PrepArgs {
    const float* W[8];
    int N[8];
    int row_off[8];
    int blk_cum[9];
};

__global__ void prep_all(PrepArgs pa, __half* __restrict__ wthi)
{
    __shared__ float tile[256][33];
    int b = blockIdx.x;
    int m = 0;
    while (b >= pa.blk_cum[m + 1]) m++;
    const int n0 = (b - pa.blk_cum[m]) * 32;
    const float* W = pa.W[m];
    const int N = pa.N[m];
    __half* out = wthi + (size_t)pa.row_off[m] * 256;

    const int tx = threadIdx.x & 31;
    const int ty = threadIdx.x >> 5;
    for (int k = ty; k < 256; k += 8)
        tile[k][tx] = W[(size_t)k * N + n0 + tx];
    __syncthreads();
    for (int nr = ty * 4; nr < ty * 4 + 4; nr++)
        for (int k = tx; k < 256; k += 32)
            out[(size_t)(n0 + nr) * 256 + k] = __float2half_rn(tile[k][nr]);
}

__global__ void split_x(const float* __restrict__ x,
                        __half* __restrict__ xh, int total4)
{
    int i = blockIdx.x * blockDim.x + threadIdx.x;
    if (i >= total4) return;
    float4 v = *(const float4*)&x[i * 4];
    uint2 p;
    p.x = packh(__float2half_rn(v.x), __float2half_rn(v.y));
    p.y = packh(__float2half_rn(v.z), __float2half_rn(v.w));
    *(uint2*)&xh[i * 4] = p;
}

// ---------------------------------------------------------------------------
// Attention: one block per node, warp per head
// ---------------------------------------------------------------------------
__global__ void attn_kernel(const __half* __restrict__ xfq,
                            const __half* __restrict__ kkvv,
                            __half* __restrict__ out,
                            int s0)
{
    const int node = blockIdx.x;
    const int d = threadIdx.x;
    const float qv = __half2float(xfq[(size_t)(s0 + node) * 512 + 256 + d]);

    float logit[4];
    #pragma unroll
    for (int k = 0; k < 4; k++) {
        float p = qv * __half2float(kkvv[((size_t)(node * 4 + k)) * 512 + d]);
        #pragma unroll
        for (int off = 16; off > 0; off >>= 1)
            p += __shfl_xor_sync(0xffffffffu, p, off);
        logit[k] = p * 0.1767766952966369f;
    }
    float mx = fmaxf(fmaxf(logit[0], logit[1]), fmaxf(logit[2], logit[3]));
    float e[4], s = 0.f;
    #pragma unroll
    for (int k = 0; k < 4; k++) { e[k] = expf(logit[k] - mx); s += e[k]; }
    const float inv = 1.f / s;

    float o = 0.f;
    #pragma unroll
    for (int k = 0; k < 4; k++)
        o += (e[k] * inv) * __half2float(kkvv[((size_t)(node * 4 + k)) * 512 + 256 + d]);
    out[(size_t)node * 256 + d] = __float2half_rn(o);
}

// ---------------------------------------------------------------------------
// Elementwise
// ---------------------------------------------------------------------------
__device__ __forceinline__ float h2f(const __half h) { return __half2float(h); }

__global__ void leaf_kernel(const __half* __restrict__ xiou,
                            float* __restrict__ h_out,
                            float* __restrict__ c_out,
                            __half* __restrict__ hh)
{
    const size_t node = LEAF_S + (size_t)blockIdx.x * 4 + (threadIdx.x >> 6);
    const int j = (threadIdx.x & 63) << 2;
    const __half2* pi = (const __half2*)&xiou[node * 768 + j];
    const __half2* po = (const __half2*)&xiou[node * 768 + 256 + j];
    const __half2* pu = (const __half2*)&xiou[node * 768 + 512 + j];
    float2 ia = __half22float2(pi[0]), ib = __half22float2(pi[1]);
    float2 oa = __half22float2(po[0]), ob = __half22float2(po[1]);
    float2 ua = __half22float2(pu[0]), ub = __half22float2(pu[1]);
    float4 c, h;
    c.x = sigm(ia.x) * tanhf(ua.x); h.x = sigm(oa.x) * tanhf(c.x);
    c.y = sigm(ia.y) * tanhf(ua.y); h.y = sigm(oa.y) * tanhf(c.y);
    c.z = sigm(ib.x) * tanhf(ub.x); h.z = sigm(ob.x) * tanhf(c.z);
    c.w = sigm(ib.y) * tanhf(ub.y); h.w = sigm(ob.y) * tanhf(c.w);
    *(float4*)&h_out[node * 256 + j] = h;
    *(float4*)&c_out[node * 256 + j] = c;
    uint2 p;
    p.x = packh(__float2half_rn(h.x), __float2half_rn(h.y));
    p.y = packh(__float2half_rn(h.z), __float2half_rn(h.w));
    *(uint2*)&hh[node * 256 + j] = p;
}

__global__ void combine_kernel(const __half* __restrict__ xiou,
                               const __half* __restrict__ xfq,
                               const __half* __restrict__ hu,
                               float* __restrict__ h_out,
                               float* __restrict__ c_out,
                               __half* __restrict__ hh,
                               int s0, int child_start)
{
    const int i = blockIdx.x;
    const int j = threadIdx.x;
    const size_t gr = (size_t)(s0 + i);

    const float ig = h2f(xiou[gr * 768 + j])       + h2f(hu[(size_t)i * 1024 + j]);
    const float og = h2f(xiou[gr * 768 + 256 + j]) + h2f(hu[(size_t)i * 1024 + 256 + j]);
    const float ug = h2f(xiou[gr * 768 + 512 + j]) + h2f(hu[(size_t)i * 1024 + 512 + j]);
    const float f  = sigm(h2f(xfq[gr * 512 + j])   + h2f(hu[(size_t)i * 1024 + 768 + j]));

    const size_t cb = (size_t)(child_start + i * 4) * 256 + j;
    const float csum = c_out[cb] + c_out[cb + 256] + c_out[cb + 512] + c_out[cb + 768];

    const float c = sigm(ig) * tanhf(ug) + f * csum;
    const float h = sigm(og) * tanhf(c);
    h_out[gr * 256 + j] = h;
    c_out[gr * 256 + j] = c;
    hh[gr * 256 + j] = __float2half_rn(h);
}

// ---------------------------------------------------------------------------
// Fused small-level kernel (n <= 64): one CTA = 2 nodes, all phases fp32.
// ---------------------------------------------------------------------------
__global__ void __launch_bounds__(512, 1)
fused_level(const __half* __restrict__ xiou,
            const __half* __restrict__ xfq,
            const float* __restrict__ Wk,  const float* __restrict__ bk_,
            const float* __restrict__ Wv,  const float* __restrict__ bv_,
            const float* __restrict__ Wl,  const float* __restrict__ bl_,
            const float* __restrict__ Uiou_w, const float* __restrict__ Uiou_b,
            const float* __restrict__ Uf_w,   const float* __restrict__ Uf_b,
            float* __restrict__ h_out, float* __restrict__ c_out,
            int s0, int cs, int n)
{
    __shared__ float chs[8][256];
    __shared__ float kvs[8][512];
    __shared__ float atts[2][256];
    __shared__ float hatts[2][256];
    __shared__ float hus[2][1024];

    const int tid = threadIdx.x;
    const int node0 = blockIdx.x * 2;
    const int nn = (n - node0) < 2 ? (n - node0) : 2;

    for (int idx = tid; idx < 4 * nn * 256; idx += 512) {
        int r = idx >> 8, k = idx & 255;
        chs[r][k] = h_out[(size_t)(cs + node0 * 4 + r) * 256 + k];
    }
    __syncthreads();

    {
        int c = tid;
        const float* W = (c < 256) ? (Wk + c) : (Wv + (c - 256));
        float acc[8] = {0, 0, 0, 0, 0, 0, 0, 0};
        int rmax = 4 * nn;
        #pragma unroll 4
        for (int k = 0; k < 256; k++) {
            float w = W[(size_t)k * 256];
            #pragma unroll
            for (int r = 0; r < 8; r++)
                acc[r] += chs[r][k] * w;
        }
        float b = (c < 256) ? bk_[c] : bv_[c - 256];
        for (int r = 0; r < rmax; r++) kvs[r][c] = acc[r] + b;
    }
    __syncthreads();

    {
        int i = tid >> 8, d = tid & 255;
        if (i < nn) {
            float qv = h2f(xfq[(size_t)(s0 + node0 + i) * 512 + 256 + d]);
            float logit[4];
            #pragma unroll
            for (int k = 0; k < 4; k++) {
                float p = qv * kvs[i * 4 + k][d];
                #pragma unroll
                for (int off = 16; off > 0; off >>= 1)
                    p += __shfl_xor_sync(0xffffffffu, p, off);
                logit[k] = p * 0.1767766952966369f;
            }
            float mx = fmaxf(fmaxf(logit[0], logit[1]), fmaxf(logit[2], logit[3]));
            float e[4], s = 0.f;
            #pragma unroll
            for (int k = 0; k < 4; k++) { e[k] = expf(logit[k] - mx); s += e[k]; }
            float inv = 1.f / s;
            float o = 0.f;
            #pragma unroll
            for (int k = 0; k < 4; k++)
                o += (e[k] * inv) * kvs[i * 4 + k][256 + d];
            atts[i][d] = o;
        }
    }
    __syncthreads();

    if (tid < 256) {
        int c = tid;
        float a0 = 0.f, a1 = 0.f;
        #pragma unroll 4
        for (int k = 0; k < 256; k++) {
            float w = Wl[(size_t)k * 256 + c];
            a0 += atts[0][k] * w;
            a1 += atts[1][k] * w;
        }
        hatts[0][c] = a0 + bl_[c];
        hatts[1][c] = a1 + bl_[c];
    }
    __syncthreads();

    #pragma unroll
    for (int pass = 0; pass < 2; pass++) {
        int cc = tid + pass * 512;
        float a0 = 0.f, a1 = 0.f, b;
        if (cc < 768) {
            #pragma unroll 4
            for (int k = 0; k < 256; k++) {
                float w = Uiou_w[(size_t)k * 768 + cc];
                a0 += hatts[0][k] * w;
                a1 += hatts[1][k] * w;
            }
            b = Uiou_b[cc];
        } else {
            int c2 = cc - 768;
            #pragma unroll 4
            for (int k = 0; k < 256; k++) {
                float w = Uf_w[(size_t)k * 256 + c2];
                a0 += hatts[0][k] * w;
                a1 += hatts[1][k] * w;
            }
            b = Uf_b[c2];
        }
        hus[0][cc] = a0 + b;
        hus[1][cc] = a1 + b;
    }
    __syncthreads();

    {
        int i = tid >> 8, j = tid & 255;
        if (i < nn) {
            size_t g = (size_t)(s0 + node0 + i);
            float ig = h2f(xiou[g * 768 + j])       + hus[i][j];
            float og = h2f(xiou[g * 768 + 256 + j]) + hus[i][256 + j];
            float ug = h2f(xiou[g * 768 + 512 + j]) + hus[i][512 + j];
            float f  = sigm(h2f(xfq[g * 512 + j])   + hus[i][768 + j]);
            size_t cb = (size_t)(cs + (node0 + i) * 4) * 256 + j;
            float csum = c_out[cb] + c_out[cb + 256] + c_out[cb + 512] + c_out[cb + 768];
            float cv = sigm(ig) * tanhf(ug) + f * csum;
            float hv = sigm(og) * tanhf(cv);
            h_out[g * 256 + j] = hv;
            c_out[g * 256 + j] = cv;
        }
    }
}

// ---------------------------------------------------------------------------
// Launch
// ---------------------------------------------------------------------------
extern "C" void kernel_launch(void* const* d_in, const int* in_sizes, int n_in,
                              void* d_out, int out_size)
{
    const float* x      = (const float*)d_in[0];
    const float* W_iou  = (const float*)d_in[1];
    const float* b_iou  = (const float*)d_in[2];
    const float* W_f    = (const float*)d_in[3];
    const float* b_f    = (const float*)d_in[4];
    const float* Wq     = (const float*)d_in[5];
    const float* bq     = (const float*)d_in[6];
    const float* Wk     = (const float*)d_in[7];
    const float* bk     = (const float*)d_in[8];
    const float* Wv     = (const float*)d_in[9];
    const float* bv     = (const float*)d_in[10];
    const float* Wl     = (const float*)d_in[11];
    const float* bl     = (const float*)d_in[12];
    const float* Uiou_w = (const float*)d_in[13];
    const float* Uiou_b = (const float*)d_in[14];
    const float* Uf_w   = (const float*)d_in[15];
    const float* Uf_b   = (const float*)d_in[16];

    float* h_out = (float*)d_out;
    float* c_out = h_out + (size_t)NN * 256;

    float *bias;
    __half *xiou, *xfq, *hu, *kkvv, *att, *hatt, *xh, *hh, *wthi;
    cudaGetSymbolAddress((void**)&xiou, g_xiou);
    cudaGetSymbolAddress((void**)&xfq,  g_xfq);
    cudaGetSymbolAddress((void**)&hu,   g_hu);
    cudaGetSymbolAddress((void**)&bias, g_bias);
    cudaGetSymbolAddress((void**)&kkvv, g_kkvv);
    cudaGetSymbolAddress((void**)&att,  g_att);
    cudaGetSymbolAddress((void**)&hatt, g_hatt);
    cudaGetSymbolAddress((void**)&xh,   g_xh);
    cudaGetSymbolAddress((void**)&hh,   g_hh);
    cudaGetSymbolAddress((void**)&wthi, g_wthi);

    cudaFuncSetAttribute(gemm_f16, cudaFuncAttributeMaxDynamicSharedMemorySize, GSMEM);

    auto GEMM = [&](const __half* A, int wt, __half* Ch, int M, int Ntot) {
        dim3 grid((M + 127) / 128, Ntot / 128);
        gemm_f16<<<grid, 256, GSMEM>>>(A, wthi + (size_t)wt * 256,
                                       bias + wt, Ch, M, Ntot);
    };

    // ---- combined weight prep (1 launch) ----
    PrepArgs pa;
    pa.W[0] = W_iou;  pa.N[0] = 768; pa.row_off[0] = WT_IOU;
    pa.W[1] = W_f;    pa.N[1] = 256; pa.row_off[1] = WT_FQ;
    pa.W[2] = Wq;     pa.N[2] = 256; pa.row_off[2] = WT_FQ + 256;
    pa.W[3] = Wk;     pa.N[3] = 256; pa.row_off[3] = WT_KV;
    pa.W[4] = Wv;     pa.N[4] = 256; pa.row_off[4] = WT_KV + 256;
    pa.W[5] = Wl;     pa.N[5] = 256; pa.row_off[5] = WT_L;
    pa.W[6] = Uiou_w; pa.N[6] = 768; pa.row_off[6] = WT_U;
    pa.W[7] = Uf_w;   pa.N[7] = 256; pa.row_off[7] = WT_U + 768;
    pa.blk_cum[0] = 0;
    for (int m = 0; m < 8; m++) pa.blk_cum[m + 1] = pa.blk_cum[m] + pa.N[m] / 32;
    prep_all<<<pa.blk_cum[8], 256>>>(pa, wthi);

    // ---- bias concat ----
    cudaMemcpyAsync(bias + WT_IOU,      b_iou,  768 * 4, cudaMemcpyDeviceToDevice, 0);
    cudaMemcpyAsync(bias + WT_FQ,       b_f,    256 * 4, cudaMemcpyDeviceToDevice, 0);
    cudaMemcpyAsync(bias + WT_FQ + 256, bq,     256 * 4, cudaMemcpyDeviceToDevice, 0);
    cudaMemcpyAsync(bias + WT_KV,       bk,     256 * 4, cudaMemcpyDeviceToDevice, 0);
    cudaMemcpyAsync(bias + WT_KV + 256, bv,     256 * 4, cudaMemcpyDeviceToDevice, 0);
    cudaMemcpyAsync(bias + WT_L,        bl,     256 * 4, cudaMemcpyDeviceToDevice, 0);
    cudaMemcpyAsync(bias + WT_U,        Uiou_b, 768 * 4, cudaMemcpyDeviceToDevice, 0);
    cudaMemcpyAsync(bias + WT_U + 768,  Uf_b,   256 * 4, cudaMemcpyDeviceToDevice, 0);

    // ---- split x, precompute GEMMs ----
    const int tot4 = NN * 256 / 4;
    split_x<<<(tot4 + 255) / 256, 256>>>(x, xh, tot4);
    GEMM(xh, WT_IOU, xiou, NN, 768);
    GEMM(xh, WT_FQ,  xfq,  NI, 512);

    // ---- leaf level ----
    leaf_kernel<<<LEAF_N / 4, 256>>>(xiou, h_out, c_out, hh);

    // ---- internal levels, bottom-up ----
    const int starts[9] = {0, 1, 5, 21, 85, 341, 1365, 5461, 21845};
    for (int l = 7; l >= 4; l--) {
        const int n  = 1 << (2 * l);
        const int s0 = starts[l];
        const int cs = starts[l + 1];
        const int nK = n * 4;
        const __half* chh = hh + (size_t)cs * 256;

        GEMM(chh, WT_KV, kkvv, nK, 512);
        attn_kernel<<<n, 256>>>(xfq, kkvv, att, s0);
        GEMM(att, WT_L, hatt, n, 256);
        GEMM(hatt, WT_U, hu, n, 1024);
        combine_kernel<<<n, 256>>>(xiou, xfq, hu, h_out, c_out, hh, s0, cs);
    }
    for (int l = 3; l >= 0; l--) {
        const int n  = 1 << (2 * l);
        fused_level<<<(n + 1) / 2, 512>>>(xiou, xfq,
                                          Wk, bk, Wv, bv, Wl, bl,
                                          Uiou_w, Uiou_b, Uf_w, Uf_b,
                                          h_out, c_out,
                                          starts[l], starts[l + 1], n);
    }
}